// round 9
// baseline (speedup 1.0000x reference)
#include <cuda_runtime.h>
#include <cuda_fp16.h>
#include <cstdint>

#define N_NODES 10000
#define N_EDGES 160000
#define F_NODE  128
#define C_GCN   64
#define S_SEQ   32
#define T_SEQ   96
#define H       128
#define NP      36             /* nodes per CTA */
#define NT      5              /* n8 tiles (40 cols, 4 pad) */
#define NBLK    296            /* 2 CTAs per SM */
#define NPAD    (NBLK*NP)      /* 10656 */
#define THREADS 256

#define XF_U    5760           /* 18 kslots x 5 ntiles x 32 lanes x 2 u32 */
#define C_U     5120           /* 128 x 40 floats per layer */
#define ZERO_U  (XF_U + 2*C_U) /* 16000 u32 */
#define W0S_U4  2048           /* 2 k16 chunks cached in smem */
#define SMEM_B  ((ZERO_U + W0S_U4*4)*4)   /* 96768 B */

// ---------------- device globals ----------------
__device__ int    g_i32;
__device__ float  g_deg [N_NODES];
__device__ float  g_xwS [N_NODES*C_GCN];
__device__ float  g_acc [N_NODES*C_GCN];
__device__ float  g_gcnT[C_GCN*N_NODES];
__device__ float4 g_gpF [NBLK*8*4*NT*32];  // [blk][w][g][nt][lane] d-frag f32x4
__device__ uint4  g_WF  [26624];           // fp16 A-frags: layer0 10240, layer1 16384

__device__ __forceinline__ int eidx(const void* ei, int idx){
  if (g_i32) return ((const int*)ei)[idx];
  return (int)((const long long*)ei)[idx];
}

// ---------------- GCN prep ----------------
__global__ void k_reset(){ g_i32 = 0; }

__global__ void k_detect(const int* ei){
  int any = 0;
  for (int i = blockIdx.x*blockDim.x + threadIdx.x; i < N_EDGES; i += gridDim.x*blockDim.x)
    any |= ei[2*i+1];
  if (__syncthreads_or(any)) { if (threadIdx.x == 0) atomicOr(&g_i32, 1); }
}

__global__ void k_init(){
  int i = blockIdx.x*blockDim.x + threadIdx.x;
  if (i < N_NODES*C_GCN){
    g_acc[i] = 0.f;
    if (i < N_NODES) g_deg[i] = 1.f;
  }
}

__global__ void k_degedge(const void* ei){
  int e = blockIdx.x*blockDim.x + threadIdx.x;
  if (e < N_EDGES) atomicAdd(&g_deg[eidx(ei, N_EDGES + e)], 1.f);
}

__global__ void k_xw(const float* __restrict__ nf, const float* __restrict__ gw){
  int idx = blockIdx.x*blockDim.x + threadIdx.x;
  if (idx >= N_NODES*C_GCN) return;
  int n = idx >> 6, c = idx & 63;
  float s = 0.f;
  #pragma unroll 8
  for (int k = 0; k < F_NODE; k++) s += nf[n*F_NODE + k] * __ldg(&gw[k*C_GCN + c]);
  g_xwS[idx] = s * rsqrtf(g_deg[n]);
}

__global__ void k_scatter(const void* ei){
  int idx = blockIdx.x*blockDim.x + threadIdx.x;
  if (idx >= N_EDGES*64) return;
  int e = idx >> 6, c = idx & 63;
  atomicAdd(&g_acc[eidx(ei, N_EDGES + e)*64 + c], g_xwS[eidx(ei, e)*64 + c]);
}

__global__ void k_gcnT(const float* __restrict__ gb){
  int idx = blockIdx.x*blockDim.x + threadIdx.x;
  if (idx >= N_NODES*C_GCN) return;
  int n = idx >> 6, c = idx & 63;
  float v = rsqrtf(g_deg[n]) * (g_acc[idx] + g_xwS[idx]) + __ldg(&gb[c]);
  g_gcnT[c*N_NODES + n] = v;
}

// gpart (gcn + both layer-0 biases) baked into D-fragment layout
__global__ void k_gpf(const float* __restrict__ wih0, const float* __restrict__ bih0,
                      const float* __restrict__ bhh0){
  int idx = blockIdx.x*blockDim.x + threadIdx.x;
  if (idx >= 512*NPAD) return;
  int m = idx / NPAD, p = idx - m*NPAD;
  int blk = p / NP, pl = p - blk*NP;
  int a = p; if (a >= N_NODES) a = N_NODES - 1;
  float s = __ldg(&bih0[m]) + __ldg(&bhh0[m]);
  #pragma unroll 8
  for (int j = 0; j < 64; j++)
    s += g_gcnT[j*N_NODES + a] * __ldg(&wih0[m*96 + 32 + j]);
  int g = m >> 7, ml = m & 127, w = ml >> 4, t8 = ml & 15, T = t8 & 7, hf = t8 >> 3;
  int nt = pl >> 3, n8 = pl & 7, cq = n8 >> 1, dn = n8 & 1;
  int lane = T*4 + cq, r = hf*2 + dn;
  ((float*)g_gpF)[((((blk*8 + w)*4 + g)*NT + nt)*32 + lane)*4 + r] = s;
}

__device__ __forceinline__ unsigned short hfbits(float v){
  __half h = __float2half_rn(v);
  return *(unsigned short*)&h;
}
__device__ __forceinline__ float hf2f(unsigned short u){
  return __half2float(*(__half*)&u);
}

// Weights pre-permuted into mma A-fragment order, single fp16.
// idx = [k16][g][w][lane][reg]; layer = (k16 >= 10)
__global__ void k_wf(const float* __restrict__ wih0, const float* __restrict__ whh0,
                     const float* __restrict__ wih1, const float* __restrict__ whh1){
  int idx = blockIdx.x*blockDim.x + threadIdx.x;
  if (idx >= 106496) return;
  int reg = idx & 3, l = (idx >> 2) & 31;
  int w = (idx >> 7) & 7, g = (idx >> 10) & 3, k16 = idx >> 12;
  int layer = (k16 >= 10);
  int k16l = layer ? k16 - 10 : k16;
  int T = l >> 2, cq = l & 3;
  int row  = T + 8*(reg & 1);
  int colb = 2*cq + 8*(reg >> 1);
  int m = g*128 + w*16 + row;
  int k = k16l*16 + colb;                 // k even; pair never straddles 128
  float v0, v1;
  if (layer){
    if (k < 128){ v0 = whh1[m*128 + k];       v1 = whh1[m*128 + k + 1]; }
    else        { v0 = wih1[m*128 + k - 128]; v1 = wih1[m*128 + k - 127]; }
  } else {
    if (k < 128){ v0 = whh0[m*128 + k];       v1 = whh0[m*128 + k + 1]; }
    else        { v0 = wih0[m*96 + k - 128];  v1 = wih0[m*96 + k - 127]; }
  }
  ((uint32_t*)g_WF)[idx] = ((uint32_t)hfbits(v1) << 16) | (uint32_t)hfbits(v0);
}

// ---------------- mega kernel ----------------
__device__ __forceinline__ float tanh_a(float x){
  float r; asm("tanh.approx.f32 %0, %1;" : "=f"(r) : "f"(x)); return r;
}
__device__ __forceinline__ float sig_a(float x){
  return fmaf(0.5f, tanh_a(0.5f*x), 0.5f);
}

__device__ __forceinline__ void mma_f16(float* d, const uint32_t* a, uint2 b){
  asm volatile("mma.sync.aligned.m16n8k16.row.col.f32.f16.f16.f32 "
               "{%0,%1,%2,%3}, {%4,%5,%6,%7}, {%8,%9}, {%0,%1,%2,%3};"
               : "+f"(d[0]), "+f"(d[1]), "+f"(d[2]), "+f"(d[3])
               : "r"(a[0]), "r"(a[1]), "r"(a[2]), "r"(a[3]), "r"(b.x), "r"(b.y));
}

// layer 0: k16 0..1 from smem cache, 2..9 streamed double-buffered
__device__ __forceinline__ void gemm_l0(const uint32_t* __restrict__ XH,
                                        const uint4* __restrict__ W0S,
                                        float acc[20][4], int o, int l){
  uint4 a_str[4];
  #pragma unroll
  for (int g = 0; g < 4; g++) a_str[g] = __ldg(&g_WF[2*1024 + g*256 + o]);
  #pragma unroll
  for (int k16 = 0; k16 < 2; k16++){
    int ks = 8 + k16;
    uint4 a_cur[4];
    #pragma unroll
    for (int g = 0; g < 4; g++) a_cur[g] = W0S[k16*1024 + g*256 + o];
    #pragma unroll
    for (int nt = 0; nt < NT; nt++){
      uint2 bh = *(const uint2*)&XH[((ks*NT + nt)*32 + l)*2];
      #pragma unroll
      for (int g = 0; g < 4; g++)
        mma_f16(acc[g*NT+nt], (const uint32_t*)&a_cur[g], bh);
    }
  }
  #pragma unroll 1
  for (int k16 = 2; k16 < 10; k16++){
    int ks = 8 + k16;
    uint4 a_cur[4];
    #pragma unroll
    for (int g = 0; g < 4; g++) a_cur[g] = a_str[g];
    if (k16 < 9){
      #pragma unroll
      for (int g = 0; g < 4; g++) a_str[g] = __ldg(&g_WF[(k16+1)*1024 + g*256 + o]);
    }
    #pragma unroll
    for (int nt = 0; nt < NT; nt++){
      uint2 bh = *(const uint2*)&XH[((ks*NT + nt)*32 + l)*2];
      #pragma unroll
      for (int g = 0; g < 4; g++)
        mma_f16(acc[g*NT+nt], (const uint32_t*)&a_cur[g], bh);
    }
  }
}

// layer 1: all 16 k16 streamed, first frag preloaded by caller (hidden under epi0)
__device__ __forceinline__ void gemm_l1(const uint32_t* __restrict__ XH,
                                        float acc[20][4], int o, int l,
                                        const uint4 a0[4]){
  const uint4* WF = g_WF + 10240;
  uint4 a_cur[4] = {a0[0], a0[1], a0[2], a0[3]};
  #pragma unroll 1
  for (int k16 = 0; k16 < 16; k16++){
    uint4 a_nxt[4];
    if (k16 < 15){
      #pragma unroll
      for (int g = 0; g < 4; g++) a_nxt[g] = __ldg(&WF[(k16+1)*1024 + g*256 + o]);
    }
    #pragma unroll
    for (int nt = 0; nt < NT; nt++){
      uint2 bh = *(const uint2*)&XH[((k16*NT + nt)*32 + l)*2];
      #pragma unroll
      for (int g = 0; g < 4; g++)
        mma_f16(acc[g*NT+nt], (const uint32_t*)&a_cur[g], bh);
    }
    #pragma unroll
    for (int g = 0; g < 4; g++) a_cur[g] = a_nxt[g];
  }
}

__device__ __forceinline__ void epilogue(float acc[20][4], float* csm,
                                         uint32_t* XH, int w, int l, int ksbase){
  int T = l >> 2, cq = l & 3;
  int ks = ksbase + w;
  int s_lo = w*16 + T, s_hi = s_lo + 8;
  #pragma unroll
  for (int nt = 0; nt < NT; nt++){
    int n0 = nt*8 + 2*cq;
    float2 cl = *(float2*)&csm[s_lo*40 + n0];
    float2 ch = *(float2*)&csm[s_hi*40 + n0];
    float cold[4] = {cl.x, cl.y, ch.x, ch.y};
    float2 nl, nh;
    #pragma unroll
    for (int r = 0; r < 4; r++){
      int half = r >> 1;
      float gi = acc[nt][r], gf = acc[NT+nt][r], gz = acc[2*NT+nt][r], go = acc[3*NT+nt][r];
      float cn = sig_a(gf)*cold[r] + sig_a(gi)*tanh_a(gz);
      if (r == 0) nl.x = cn; else if (r == 1) nl.y = cn;
      else if (r == 2) nh.x = cn; else nh.y = cn;
      float h = sig_a(go)*tanh_a(cn);
      int n = n0 + (r & 1);
      int lane = ((n & 7) << 2) + (T >> 1);
      int ui = ((ks*NT + nt)*32 + lane)*2 + half;
      ((unsigned short*)&XH[ui])[T & 1] = hfbits(h);
    }
    *(float2*)&csm[s_lo*40 + n0] = nl;
    *(float2*)&csm[s_hi*40 + n0] = nh;
  }
}

__device__ __forceinline__ void stage_seq(const float* __restrict__ seq, int base, int t,
                                          uint32_t* XH, int tid){
  for (int idx = tid; idx < NP*S_SEQ; idx += THREADS){
    int nl = idx >> 5, i = idx & 31;
    int a = base + nl; if (a >= N_NODES) a = N_NODES - 1;
    float v = seq[(size_t)a*(T_SEQ*S_SEQ) + t*S_SEQ + i];
    int ks = 16 + (i >> 4), kl = i & 15;
    int r = kl >> 3, cq = (kl & 7) >> 1, hf = kl & 1;
    int lane = ((nl & 7) << 2) + cq;
    int nt = nl >> 3;
    int ui = ((ks*NT + nt)*32 + lane)*2 + r;
    ((unsigned short*)&XH[ui])[hf] = hfbits(v);
  }
}

__global__ void __launch_bounds__(THREADS, 2)
k_mega(const float* __restrict__ seq, const float* __restrict__ bih1,
       const float* __restrict__ bhh1, const float* __restrict__ fcw,
       const float* __restrict__ fcb, float* __restrict__ out){
  extern __shared__ uint32_t smu[];
  uint32_t* XH = smu;
  float* c0 = (float*)(smu + XF_U);
  float* c1 = c0 + C_U;
  uint4* W0S = (uint4*)(smu + ZERO_U);
  int tid = threadIdx.x, w = tid >> 5, l = tid & 31;
  int blk = blockIdx.x, base = blk*NP;
  int T = l >> 2, o = w*32 + l;

  for (int i = tid; i < ZERO_U; i += THREADS) smu[i] = 0;
  for (int i = tid; i < W0S_U4; i += THREADS) W0S[i] = g_WF[i];
  __syncthreads();
  stage_seq(seq, base, 0, XH, tid);

  float b1v[4][2];
  #pragma unroll
  for (int g = 0; g < 4; g++)
    #pragma unroll
    for (int hf = 0; hf < 2; hf++){
      int m = g*128 + w*16 + T + 8*hf;
      b1v[g][hf] = __ldg(&bih1[m]) + __ldg(&bhh1[m]);
    }
  __syncthreads();

  const float4* gp = g_gpF + (blk*8 + w)*(4*NT*32);

  for (int t = 0; t < T_SEQ; t++){
    float acc[20][4];
    #pragma unroll
    for (int g = 0; g < 4; g++)
      #pragma unroll
      for (int nt = 0; nt < NT; nt++){
        float4 v = __ldg(&gp[(g*NT + nt)*32 + l]);
        acc[g*NT+nt][0] = v.x; acc[g*NT+nt][1] = v.y;
        acc[g*NT+nt][2] = v.z; acc[g*NT+nt][3] = v.w;
      }
    gemm_l0(XH, W0S, acc, o, l);
    __syncthreads();
    // prefetch layer-1's first A-frags; latency hidden under epilogue-0
    uint4 a1[4];
    #pragma unroll
    for (int g = 0; g < 4; g++) a1[g] = __ldg(&g_WF[10240 + g*256 + o]);
    epilogue(acc, c0, XH, w, l, 8);
    if (t + 1 < T_SEQ) stage_seq(seq, base, t + 1, XH, tid);
    __syncthreads();

    #pragma unroll
    for (int g = 0; g < 4; g++)
      #pragma unroll
      for (int nt = 0; nt < NT; nt++){
        acc[g*NT+nt][0] = b1v[g][0]; acc[g*NT+nt][1] = b1v[g][0];
        acc[g*NT+nt][2] = b1v[g][1]; acc[g*NT+nt][3] = b1v[g][1];
      }
    gemm_l1(XH, acc, o, l, a1);
    __syncthreads();
    epilogue(acc, c1, XH, w, l, 0);
    // no sync needed: h1 slots (0..7) are not read until after two later syncs
  }
  __syncthreads();

  if (tid < NP){
    int a = base + tid;
    if (a < N_NODES){
      float sum = __ldg(fcb);
      int nt = tid >> 3, lanebase = (tid & 7) << 2;
      #pragma unroll 8
      for (int s = 0; s < H; s++){
        int ks = s >> 4, kl = s & 15, r = kl >> 3, cq = (kl & 7) >> 1, hf = kl & 1;
        int ui = ((ks*NT + nt)*32 + lanebase + cq)*2 + r;
        sum += hf2f(((unsigned short*)&XH[ui])[hf]) * __ldg(&fcw[s]);
      }
      out[a] = sum;
    }
  }
}

// ---------------- launch ----------------
extern "C" void kernel_launch(void* const* d_in, const int* in_sizes, int n_in,
                              void* d_out, int out_size){
  const float* seq  = (const float*)d_in[0];
  const void*  ei   = d_in[1];
  const float* nf   = (const float*)d_in[3];
  const float* gw   = (const float*)d_in[5];
  const float* gb   = (const float*)d_in[6];
  const float* wih0 = (const float*)d_in[7];
  const float* whh0 = (const float*)d_in[8];
  const float* bih0 = (const float*)d_in[9];
  const float* bhh0 = (const float*)d_in[10];
  const float* wih1 = (const float*)d_in[11];
  const float* whh1 = (const float*)d_in[12];
  const float* bih1 = (const float*)d_in[13];
  const float* bhh1 = (const float*)d_in[14];
  const float* fcw  = (const float*)d_in[15];
  const float* fcb  = (const float*)d_in[16];
  float* out = (float*)d_out;

  k_reset<<<1,1>>>();
  k_detect<<<64,256>>>((const int*)ei);
  k_init<<<(N_NODES*C_GCN + 255)/256, 256>>>();
  k_degedge<<<(N_EDGES + 255)/256, 256>>>(ei);
  k_xw<<<(N_NODES*C_GCN + 255)/256, 256>>>(nf, gw);
  k_scatter<<<(N_EDGES*64 + 255)/256, 256>>>(ei);
  k_gcnT<<<(N_NODES*C_GCN + 255)/256, 256>>>(gb);
  k_gpf<<<(512*NPAD + 255)/256, 256>>>(wih0, bih0, bhh0);
  k_wf<<<(106496 + 255)/256, 256>>>(wih0, whh0, wih1, whh1);

  cudaFuncSetAttribute(k_mega, cudaFuncAttributeMaxDynamicSharedMemorySize, SMEM_B);
  k_mega<<<NBLK, THREADS, SMEM_B>>>(seq, bih1, bhh1, fcw, fcb, out);
}

// round 10
// speedup vs baseline: 1.2826x; 1.2826x over previous
#include <cuda_runtime.h>
#include <cuda_fp16.h>
#include <cstdint>

#define N_NODES 10000
#define N_EDGES 160000
#define F_NODE  128
#define C_GCN   64
#define S_SEQ   32
#define T_SEQ   96
#define H       128
#define NP      72
#define NBLK    148
#define NPAD    (NBLK*NP)      /* 10656 */
#define THREADS 256

#define XF_U    10368          /* 18 kslots x 9 ntiles x 32 lanes x 2 u32 */
#define ZERO_U  (XF_U + 2*9216)            /* XH + c0 + c1 = 28800 u32 */
#define W0S_U4  3072                       /* 3 static k16 chunks */
#define RING_U4 3072                       /* 3-slot cp.async ring */
#define SMEM_B  ((ZERO_U + (W0S_U4 + RING_U4)*4)*4)   /* 213504 B */

// ---------------- device globals ----------------
__device__ int    g_i32;
__device__ float  g_deg [N_NODES];
__device__ float  g_xwS [N_NODES*C_GCN];
__device__ float  g_acc [N_NODES*C_GCN];
__device__ float  g_gcnT[C_GCN*N_NODES];
__device__ float4 g_gpF [NBLK*8*4*9*32];   // [blk][w][g][nt][lane] d-frag f32x4
__device__ uint4  g_WF  [26624];           // fp16 A-frags: layer0 10240, layer1 16384

__device__ __forceinline__ int eidx(const void* ei, int idx){
  if (g_i32) return ((const int*)ei)[idx];
  return (int)((const long long*)ei)[idx];
}

// ---------------- GCN prep ----------------
__global__ void k_reset(){ g_i32 = 0; }

__global__ void k_detect(const int* ei){
  int any = 0;
  for (int i = blockIdx.x*blockDim.x + threadIdx.x; i < N_EDGES; i += gridDim.x*blockDim.x)
    any |= ei[2*i+1];
  if (__syncthreads_or(any)) { if (threadIdx.x == 0) atomicOr(&g_i32, 1); }
}

__global__ void k_init(){
  int i = blockIdx.x*blockDim.x + threadIdx.x;
  if (i < N_NODES*C_GCN){
    g_acc[i] = 0.f;
    if (i < N_NODES) g_deg[i] = 1.f;
  }
}

__global__ void k_degedge(const void* ei){
  int e = blockIdx.x*blockDim.x + threadIdx.x;
  if (e < N_EDGES) atomicAdd(&g_deg[eidx(ei, N_EDGES + e)], 1.f);
}

__global__ void k_xw(const float* __restrict__ nf, const float* __restrict__ gw){
  int idx = blockIdx.x*blockDim.x + threadIdx.x;
  if (idx >= N_NODES*C_GCN) return;
  int n = idx >> 6, c = idx & 63;
  float s = 0.f;
  #pragma unroll 8
  for (int k = 0; k < F_NODE; k++) s += nf[n*F_NODE + k] * __ldg(&gw[k*C_GCN + c]);
  g_xwS[idx] = s * rsqrtf(g_deg[n]);
}

__global__ void k_scatter(const void* ei){
  int idx = blockIdx.x*blockDim.x + threadIdx.x;
  if (idx >= N_EDGES*64) return;
  int e = idx >> 6, c = idx & 63;
  atomicAdd(&g_acc[eidx(ei, N_EDGES + e)*64 + c], g_xwS[eidx(ei, e)*64 + c]);
}

__global__ void k_gcnT(const float* __restrict__ gb){
  int idx = blockIdx.x*blockDim.x + threadIdx.x;
  if (idx >= N_NODES*C_GCN) return;
  int n = idx >> 6, c = idx & 63;
  float v = rsqrtf(g_deg[n]) * (g_acc[idx] + g_xwS[idx]) + __ldg(&gb[c]);
  g_gcnT[c*N_NODES + n] = v;
}

// gpart (gcn + both layer-0 biases) baked into D-fragment layout
__global__ void k_gpf(const float* __restrict__ wih0, const float* __restrict__ bih0,
                      const float* __restrict__ bhh0){
  int idx = blockIdx.x*blockDim.x + threadIdx.x;
  if (idx >= 512*NPAD) return;
  int m = idx / NPAD, p = idx - m*NPAD;
  int blk = p / NP, pl = p - blk*NP;
  int a = p; if (a >= N_NODES) a = N_NODES - 1;
  float s = __ldg(&bih0[m]) + __ldg(&bhh0[m]);
  #pragma unroll 8
  for (int j = 0; j < 64; j++)
    s += g_gcnT[j*N_NODES + a] * __ldg(&wih0[m*96 + 32 + j]);
  int g = m >> 7, ml = m & 127, w = ml >> 4, t8 = ml & 15, T = t8 & 7, hf = t8 >> 3;
  int nt = pl >> 3, n8 = pl & 7, cq = n8 >> 1, dn = n8 & 1;
  int lane = T*4 + cq, r = hf*2 + dn;
  ((float*)g_gpF)[((((blk*8 + w)*4 + g)*9 + nt)*32 + lane)*4 + r] = s;
}

__device__ __forceinline__ unsigned short hfbits(float v){
  __half h = __float2half_rn(v);
  return *(unsigned short*)&h;
}
__device__ __forceinline__ float hf2f(unsigned short u){
  return __half2float(*(__half*)&u);
}

// Weights pre-permuted into mma A-fragment order, single fp16.
// idx = [k16][g][w][lane][reg]; layer = (k16 >= 10)
__global__ void k_wf(const float* __restrict__ wih0, const float* __restrict__ whh0,
                     const float* __restrict__ wih1, const float* __restrict__ whh1){
  int idx = blockIdx.x*blockDim.x + threadIdx.x;
  if (idx >= 106496) return;
  int reg = idx & 3, l = (idx >> 2) & 31;
  int w = (idx >> 7) & 7, g = (idx >> 10) & 3, k16 = idx >> 12;
  int layer = (k16 >= 10);
  int k16l = layer ? k16 - 10 : k16;
  int T = l >> 2, cq = l & 3;
  int row  = T + 8*(reg & 1);
  int colb = 2*cq + 8*(reg >> 1);
  int m = g*128 + w*16 + row;
  int k = k16l*16 + colb;                 // k even; pair never straddles 128
  float v0, v1;
  if (layer){
    if (k < 128){ v0 = whh1[m*128 + k];       v1 = whh1[m*128 + k + 1]; }
    else        { v0 = wih1[m*128 + k - 128]; v1 = wih1[m*128 + k - 127]; }
  } else {
    if (k < 128){ v0 = whh0[m*128 + k];       v1 = whh0[m*128 + k + 1]; }
    else        { v0 = wih0[m*96 + k - 128];  v1 = wih0[m*96 + k - 127]; }
  }
  ((uint32_t*)g_WF)[idx] = ((uint32_t)hfbits(v1) << 16) | (uint32_t)hfbits(v0);
}

// ---------------- mega kernel ----------------
__device__ __forceinline__ float tanh_a(float x){
  float r; asm("tanh.approx.f32 %0, %1;" : "=f"(r) : "f"(x)); return r;
}
__device__ __forceinline__ float sig_a(float x){
  return fmaf(0.5f, tanh_a(0.5f*x), 0.5f);
}

__device__ __forceinline__ void mma_f16(float* d, const uint32_t* a, uint2 b){
  asm volatile("mma.sync.aligned.m16n8k16.row.col.f32.f16.f16.f32 "
               "{%0,%1,%2,%3}, {%4,%5,%6,%7}, {%8,%9}, {%0,%1,%2,%3};"
               : "+f"(d[0]), "+f"(d[1]), "+f"(d[2]), "+f"(d[3])
               : "r"(a[0]), "r"(a[1]), "r"(a[2]), "r"(a[3]), "r"(b.x), "r"(b.y));
}

// one k16 chunk against all 9 n-tiles and 4 gates
__device__ __forceinline__ void mma_block(const uint32_t* __restrict__ XH,
                                          const uint4 a[4], float acc[36][4],
                                          int ks, int l){
  #pragma unroll
  for (int nt = 0; nt < 9; nt++){
    uint2 bh = *(const uint2*)&XH[((ks*9 + nt)*32 + l)*2];
    #pragma unroll
    for (int g = 0; g < 4; g++)
      mma_f16(acc[g*9+nt], (const uint32_t*)&a[g], bh);
  }
}

__device__ __forceinline__ void ld_frags(uint4 a[4], const uint4* __restrict__ base, int o){
  #pragma unroll
  for (int g = 0; g < 4; g++) a[g] = base[g*256 + o];
}

// issue one k16 chunk into the ring; streamed ids per step are p+3 (p in 0..22)
__device__ __forceinline__ void cp_issue(uint32_t ring_addr, int slot, int p, int o){
  const char* src = (const char*)(g_WF + (p + 3)*1024 + o);
  uint32_t dst = ring_addr + (uint32_t)(slot*16384 + o*16);
  #pragma unroll
  for (int g = 0; g < 4; g++){
    asm volatile("{ .reg .u64 gp; cvta.to.global.u64 gp, %1;"
                 " cp.async.cg.shared.global [%0], [gp], 16; }"
                 :: "r"(dst + g*4096), "l"(src + (size_t)g*4096) : "memory");
  }
  asm volatile("cp.async.commit_group;" ::: "memory");
}

#define PIPE_STEP(KS) do { \
  int sI = sA + 2; if (sI >= 3) sI -= 3; \
  int pI = pA + 2; if (pI >= 23) pI -= 23; \
  cp_issue(ring_addr, sI, pI, o); \
  mma_block(XH, a_cur, acc, (KS), l); \
  asm volatile("cp.async.wait_group 1;" ::: "memory"); \
  sA = (sA + 1 == 3) ? 0 : sA + 1; \
  pA = (pA + 1 == 23) ? 0 : pA + 1; \
  ld_frags(a_cur, Wring + sA*1024, o); \
} while(0)

__device__ __forceinline__ void epilogue(float acc[36][4], float* csm,
                                         uint32_t* XH, int w, int l, int ksbase){
  int T = l >> 2, cq = l & 3;
  int ks = ksbase + w;
  int s_lo = w*16 + T, s_hi = s_lo + 8;
  #pragma unroll
  for (int nt = 0; nt < 9; nt++){
    int n0 = nt*8 + 2*cq;
    float2 cl = *(float2*)&csm[s_lo*NP + n0];
    float2 ch = *(float2*)&csm[s_hi*NP + n0];
    float cold[4] = {cl.x, cl.y, ch.x, ch.y};
    float2 nl, nh;
    #pragma unroll
    for (int r = 0; r < 4; r++){
      int half = r >> 1;
      float gi = acc[nt][r], gf = acc[9+nt][r], gz = acc[18+nt][r], go = acc[27+nt][r];
      float cn = sig_a(gf)*cold[r] + sig_a(gi)*tanh_a(gz);
      if (r == 0) nl.x = cn; else if (r == 1) nl.y = cn;
      else if (r == 2) nh.x = cn; else nh.y = cn;
      float h = sig_a(go)*tanh_a(cn);
      int n = n0 + (r & 1);
      int lane = ((n & 7) << 2) + (T >> 1);
      int ui = ((ks*9 + nt)*32 + lane)*2 + half;
      ((unsigned short*)&XH[ui])[T & 1] = hfbits(h);
    }
    *(float2*)&csm[s_lo*NP + n0] = nl;
    *(float2*)&csm[s_hi*NP + n0] = nh;
  }
}

__device__ __forceinline__ void stage_seq(const float* __restrict__ seq, int base, int t,
                                          uint32_t* XH, int tid){
  for (int idx = tid; idx < NP*S_SEQ; idx += THREADS){
    int nl = idx >> 5, i = idx & 31;
    int a = base + nl; if (a >= N_NODES) a = N_NODES - 1;
    float v = seq[(size_t)a*(T_SEQ*S_SEQ) + t*S_SEQ + i];
    int ks = 16 + (i >> 4), kl = i & 15;
    int r = kl >> 3, cq = (kl & 7) >> 1, hf = kl & 1;
    int lane = ((nl & 7) << 2) + cq;
    int nt = nl >> 3;
    int ui = ((ks*9 + nt)*32 + lane)*2 + r;
    ((unsigned short*)&XH[ui])[hf] = hfbits(v);
  }
}

__global__ void __launch_bounds__(THREADS)
k_mega(const float* __restrict__ seq, const float* __restrict__ bih1,
       const float* __restrict__ bhh1, const float* __restrict__ fcw,
       const float* __restrict__ fcb, float* __restrict__ out){
  extern __shared__ uint32_t smu[];
  uint32_t* XH = smu;
  float* c0 = (float*)(smu + XF_U);
  float* c1 = c0 + 9216;
  uint4* W0S   = (uint4*)(smu + ZERO_U);
  uint4* Wring = W0S + W0S_U4;
  int tid = threadIdx.x, w = tid >> 5, l = tid & 31;
  int blk = blockIdx.x, base = blk*NP;
  int T = l >> 2, o = w*32 + l;
  uint32_t ring_addr;
  asm("{ .reg .u64 t; cvta.to.shared.u64 t, %1; cvt.u32.u64 %0, t; }"
      : "=r"(ring_addr) : "l"((const void*)Wring));

  for (int i = tid; i < ZERO_U; i += THREADS) smu[i] = 0;
  for (int i = tid; i < W0S_U4; i += THREADS) W0S[i] = g_WF[i];  // static chunks 0..2
  __syncthreads();
  stage_seq(seq, base, 0, XH, tid);

  float b1v[4][2];
  #pragma unroll
  for (int g = 0; g < 4; g++)
    #pragma unroll
    for (int hf = 0; hf < 2; hf++){
      int m = g*128 + w*16 + T + 8*hf;
      b1v[g][hf] = __ldg(&bih1[m]) + __ldg(&bhh1[m]);
    }
  __syncthreads();

  // ---- cp.async pipeline prologue: chunks p=0,1 in flight; a_cur <- p=0 ----
  uint4 a_cur[4];
  int sA = 0, pA = 0;
  cp_issue(ring_addr, 0, 0, o);
  cp_issue(ring_addr, 1, 1, o);
  asm volatile("cp.async.wait_group 1;" ::: "memory");
  ld_frags(a_cur, Wring, o);

  const float4* gp = g_gpF + (blk*8 + w)*1152;

  for (int t = 0; t < T_SEQ; t++){
    float acc[36][4];
    #pragma unroll
    for (int g = 0; g < 4; g++)
      #pragma unroll
      for (int nt = 0; nt < 9; nt++){
        float4 v = __ldg(&gp[g*288 + nt*32 + l]);
        acc[g*9+nt][0] = v.x; acc[g*9+nt][1] = v.y;
        acc[g*9+nt][2] = v.z; acc[g*9+nt][3] = v.w;
      }
    // ---- layer 0: static chunks 0..2 (ks 8..10), streamed 3..9 (ks 11..17) ----
    {
      uint4 s_cur[4], s_nxt[4];
      ld_frags(s_cur, W0S, o);
      #pragma unroll
      for (int k = 0; k < 3; k++){
        if (k < 2) ld_frags(s_nxt, W0S + (k+1)*1024, o);
        mma_block(XH, s_cur, acc, 8 + k, l);
        #pragma unroll
        for (int g = 0; g < 4; g++) s_cur[g] = s_nxt[g];
      }
    }
    #pragma unroll 1
    for (int j = 0; j < 7; j++) PIPE_STEP(11 + j);
    __syncthreads();
    epilogue(acc, c0, XH, w, l, 8);
    if (t + 1 < T_SEQ) stage_seq(seq, base, t + 1, XH, tid);
    __syncthreads();

    // ---- layer 1: streamed chunks (ks 0..15) ----
    #pragma unroll
    for (int g = 0; g < 4; g++)
      #pragma unroll
      for (int nt = 0; nt < 9; nt++){
        acc[g*9+nt][0] = b1v[g][0]; acc[g*9+nt][1] = b1v[g][0];
        acc[g*9+nt][2] = b1v[g][1]; acc[g*9+nt][3] = b1v[g][1];
      }
    #pragma unroll 1
    for (int j = 0; j < 16; j++) PIPE_STEP(j);
    __syncthreads();
    epilogue(acc, c1, XH, w, l, 0);
    // no sync needed: h1 slots (0..7) are not read until after two later syncs
  }
  asm volatile("cp.async.wait_group 0;" ::: "memory");
  __syncthreads();

  if (tid < NP){
    int a = base + tid;
    if (a < N_NODES){
      float sum = __ldg(fcb);
      int nt = tid >> 3, lanebase = (tid & 7) << 2;
      #pragma unroll 8
      for (int s = 0; s < H; s++){
        int ks = s >> 4, kl = s & 15, r = kl >> 3, cq = (kl & 7) >> 1, hf = kl & 1;
        int ui = ((ks*9 + nt)*32 + lanebase + cq)*2 + r;
        sum += hf2f(((unsigned short*)&XH[ui])[hf]) * __ldg(&fcw[s]);
      }
      out[a] = sum;
    }
  }
}

// ---------------- launch ----------------
extern "C" void kernel_launch(void* const* d_in, const int* in_sizes, int n_in,
                              void* d_out, int out_size){
  const float* seq  = (const float*)d_in[0];
  const void*  ei   = d_in[1];
  const float* nf   = (const float*)d_in[3];
  const float* gw   = (const float*)d_in[5];
  const float* gb   = (const float*)d_in[6];
  const float* wih0 = (const float*)d_in[7];
  const float* whh0 = (const float*)d_in[8];
  const float* bih0 = (const float*)d_in[9];
  const float* bhh0 = (const float*)d_in[10];
  const float* wih1 = (const float*)d_in[11];
  const float* whh1 = (const float*)d_in[12];
  const float* bih1 = (const float*)d_in[13];
  const float* bhh1 = (const float*)d_in[14];
  const float* fcw  = (const float*)d_in[15];
  const float* fcb  = (const float*)d_in[16];
  float* out = (float*)d_out;

  k_reset<<<1,1>>>();
  k_detect<<<64,256>>>((const int*)ei);
  k_init<<<(N_NODES*C_GCN + 255)/256, 256>>>();
  k_degedge<<<(N_EDGES + 255)/256, 256>>>(ei);
  k_xw<<<(N_NODES*C_GCN + 255)/256, 256>>>(nf, gw);
  k_scatter<<<(N_EDGES*64 + 255)/256, 256>>>(ei);
  k_gcnT<<<(N_NODES*C_GCN + 255)/256, 256>>>(gb);
  k_gpf<<<(512*NPAD + 255)/256, 256>>>(wih0, bih0, bhh0);
  k_wf<<<(106496 + 255)/256, 256>>>(wih0, whh0, wih1, whh1);

  cudaFuncSetAttribute(k_mega, cudaFuncAttributeMaxDynamicSharedMemorySize, SMEM_B);
  k_mega<<<NBLK, THREADS, SMEM_B>>>(seq, bih1, bhh1, fcw, fcb, out);
}

// round 11
// speedup vs baseline: 1.2867x; 1.0032x over previous
#include <cuda_runtime.h>
#include <cuda_fp16.h>
#include <cstdint>

#define N_NODES 10000
#define N_EDGES 160000
#define F_NODE  128
#define C_GCN   64
#define S_SEQ   32
#define T_SEQ   96
#define H       128
#define NP      72
#define NBLK    148
#define NPAD    (NBLK*NP)      /* 10656 */
#define THREADS 256

#define XF_U    10368          /* 18 kslots x 9 ntiles x 32 lanes x 2 u32 */
#define ZERO_U  (XF_U + 2*9216)            /* XH + c0 + c1 = 28800 u32 */
#define W0S_U4  3072                       /* 3 static k16 chunks */
#define RING_U4 3072                       /* 3-slot cp.async ring */
#define SMEM_B  ((ZERO_U + (W0S_U4 + RING_U4)*4)*4)   /* 213504 B */

// ---------------- device globals ----------------
__device__ int    g_i32;
__device__ float  g_deg [N_NODES];
__device__ float  g_xwS [N_NODES*C_GCN];
__device__ float  g_acc [N_NODES*C_GCN];
__device__ float  g_gcnT[C_GCN*N_NODES];
__device__ float4 g_gpF [NBLK*8*4*9*32];   // [blk][w][g][nt][lane] d-frag f32x4
__device__ uint4  g_WF  [26624];           // fp16 A-frags: layer0 10240, layer1 16384

__device__ __forceinline__ int eidx(const void* ei, int idx){
  if (g_i32) return ((const int*)ei)[idx];
  return (int)((const long long*)ei)[idx];
}

// ---------------- GCN prep ----------------
__global__ void k_reset(){ g_i32 = 0; }

__global__ void k_detect(const int* ei){
  int any = 0;
  for (int i = blockIdx.x*blockDim.x + threadIdx.x; i < N_EDGES; i += gridDim.x*blockDim.x)
    any |= ei[2*i+1];
  if (__syncthreads_or(any)) { if (threadIdx.x == 0) atomicOr(&g_i32, 1); }
}

__global__ void k_init(){
  int i = blockIdx.x*blockDim.x + threadIdx.x;
  if (i < N_NODES*C_GCN){
    g_acc[i] = 0.f;
    if (i < N_NODES) g_deg[i] = 1.f;
  }
}

__global__ void k_degedge(const void* ei){
  int e = blockIdx.x*blockDim.x + threadIdx.x;
  if (e < N_EDGES) atomicAdd(&g_deg[eidx(ei, N_EDGES + e)], 1.f);
}

__global__ void k_xw(const float* __restrict__ nf, const float* __restrict__ gw){
  int idx = blockIdx.x*blockDim.x + threadIdx.x;
  if (idx >= N_NODES*C_GCN) return;
  int n = idx >> 6, c = idx & 63;
  float s = 0.f;
  #pragma unroll 8
  for (int k = 0; k < F_NODE; k++) s += nf[n*F_NODE + k] * __ldg(&gw[k*C_GCN + c]);
  g_xwS[idx] = s * rsqrtf(g_deg[n]);
}

__global__ void k_scatter(const void* ei){
  int idx = blockIdx.x*blockDim.x + threadIdx.x;
  if (idx >= N_EDGES*64) return;
  int e = idx >> 6, c = idx & 63;
  atomicAdd(&g_acc[eidx(ei, N_EDGES + e)*64 + c], g_xwS[eidx(ei, e)*64 + c]);
}

__global__ void k_gcnT(const float* __restrict__ gb){
  int idx = blockIdx.x*blockDim.x + threadIdx.x;
  if (idx >= N_NODES*C_GCN) return;
  int n = idx >> 6, c = idx & 63;
  float v = rsqrtf(g_deg[n]) * (g_acc[idx] + g_xwS[idx]) + __ldg(&gb[c]);
  g_gcnT[c*N_NODES + n] = v;
}

// gpart (gcn + both layer-0 biases) baked into D-fragment layout
__global__ void k_gpf(const float* __restrict__ wih0, const float* __restrict__ bih0,
                      const float* __restrict__ bhh0){
  int idx = blockIdx.x*blockDim.x + threadIdx.x;
  if (idx >= 512*NPAD) return;
  int m = idx / NPAD, p = idx - m*NPAD;
  int blk = p / NP, pl = p - blk*NP;
  int a = p; if (a >= N_NODES) a = N_NODES - 1;
  float s = __ldg(&bih0[m]) + __ldg(&bhh0[m]);
  #pragma unroll 8
  for (int j = 0; j < 64; j++)
    s += g_gcnT[j*N_NODES + a] * __ldg(&wih0[m*96 + 32 + j]);
  int g = m >> 7, ml = m & 127, w = ml >> 4, t8 = ml & 15, T = t8 & 7, hf = t8 >> 3;
  int nt = pl >> 3, n8 = pl & 7, cq = n8 >> 1, dn = n8 & 1;
  int lane = T*4 + cq, r = hf*2 + dn;
  ((float*)g_gpF)[((((blk*8 + w)*4 + g)*9 + nt)*32 + lane)*4 + r] = s;
}

__device__ __forceinline__ unsigned short hfbits(float v){
  __half h = __float2half_rn(v);
  return *(unsigned short*)&h;
}
__device__ __forceinline__ float hf2f(unsigned short u){
  return __half2float(*(__half*)&u);
}

// Weights pre-permuted into mma A-fragment order, single fp16.
// idx = [k16][g][w][lane][reg]; layer = (k16 >= 10)
__global__ void k_wf(const float* __restrict__ wih0, const float* __restrict__ whh0,
                     const float* __restrict__ wih1, const float* __restrict__ whh1){
  int idx = blockIdx.x*blockDim.x + threadIdx.x;
  if (idx >= 106496) return;
  int reg = idx & 3, l = (idx >> 2) & 31;
  int w = (idx >> 7) & 7, g = (idx >> 10) & 3, k16 = idx >> 12;
  int layer = (k16 >= 10);
  int k16l = layer ? k16 - 10 : k16;
  int T = l >> 2, cq = l & 3;
  int row  = T + 8*(reg & 1);
  int colb = 2*cq + 8*(reg >> 1);
  int m = g*128 + w*16 + row;
  int k = k16l*16 + colb;                 // k even; pair never straddles 128
  float v0, v1;
  if (layer){
    if (k < 128){ v0 = whh1[m*128 + k];       v1 = whh1[m*128 + k + 1]; }
    else        { v0 = wih1[m*128 + k - 128]; v1 = wih1[m*128 + k - 127]; }
  } else {
    if (k < 128){ v0 = whh0[m*128 + k];       v1 = whh0[m*128 + k + 1]; }
    else        { v0 = wih0[m*96 + k - 128];  v1 = wih0[m*96 + k - 127]; }
  }
  ((uint32_t*)g_WF)[idx] = ((uint32_t)hfbits(v1) << 16) | (uint32_t)hfbits(v0);
}

// ---------------- mega kernel ----------------
__device__ __forceinline__ float tanh_a(float x){
  float r; asm("tanh.approx.f32 %0, %1;" : "=f"(r) : "f"(x)); return r;
}
__device__ __forceinline__ float sig_a(float x){
  return fmaf(0.5f, tanh_a(0.5f*x), 0.5f);
}

__device__ __forceinline__ void mma_f16(float* d, const uint32_t* a, uint2 b){
  asm volatile("mma.sync.aligned.m16n8k16.row.col.f32.f16.f16.f32 "
               "{%0,%1,%2,%3}, {%4,%5,%6,%7}, {%8,%9}, {%0,%1,%2,%3};"
               : "+f"(d[0]), "+f"(d[1]), "+f"(d[2]), "+f"(d[3])
               : "r"(a[0]), "r"(a[1]), "r"(a[2]), "r"(a[3]), "r"(b.x), "r"(b.y));
}

// one k16 chunk against all 9 n-tiles and 4 gates
__device__ __forceinline__ void mma_block(const uint32_t* __restrict__ XH,
                                          const uint4 a[4], float acc[36][4],
                                          int ks, int l){
  #pragma unroll
  for (int nt = 0; nt < 9; nt++){
    uint2 bh = *(const uint2*)&XH[((ks*9 + nt)*32 + l)*2];
    #pragma unroll
    for (int g = 0; g < 4; g++)
      mma_f16(acc[g*9+nt], (const uint32_t*)&a[g], bh);
  }
}

__device__ __forceinline__ void ld_frags(uint4 a[4], const uint4* __restrict__ base, int o){
  #pragma unroll
  for (int g = 0; g < 4; g++) a[g] = base[g*256 + o];
}

// issue one k16 chunk into the ring; streamed ids per step are p+3 (p in 0..22)
__device__ __forceinline__ void cp_issue(uint32_t ring_addr, int slot, int p, int o){
  const char* src = (const char*)(g_WF + (p + 3)*1024 + o);
  uint32_t dst = ring_addr + (uint32_t)(slot*16384 + o*16);
  #pragma unroll
  for (int g = 0; g < 4; g++){
    asm volatile("{ .reg .u64 gp; cvta.to.global.u64 gp, %1;"
                 " cp.async.cg.shared.global [%0], [gp], 16; }"
                 :: "r"(dst + g*4096), "l"(src + (size_t)g*4096) : "memory");
  }
  asm volatile("cp.async.commit_group;" ::: "memory");
}

#define PIPE_STEP(ACC, KS) do { \
  int sI = sA + 2; if (sI >= 3) sI -= 3; \
  int pI = pA + 2; if (pI >= 23) pI -= 23; \
  cp_issue(ring_addr, sI, pI, o); \
  mma_block(XH, a_cur, (ACC), (KS), l); \
  asm volatile("cp.async.wait_group 1;" ::: "memory"); \
  sA = (sA + 1 == 3) ? 0 : sA + 1; \
  pA = (pA + 1 == 23) ? 0 : pA + 1; \
  ld_frags(a_cur, Wring + sA*1024, o); \
} while(0)

__device__ __forceinline__ void epilogue(float acc[36][4], float* csm,
                                         uint32_t* XH, int w, int l, int ksbase){
  int T = l >> 2, cq = l & 3;
  int ks = ksbase + w;
  int s_lo = w*16 + T, s_hi = s_lo + 8;
  #pragma unroll
  for (int nt = 0; nt < 9; nt++){
    int n0 = nt*8 + 2*cq;
    float2 cl = *(float2*)&csm[s_lo*NP + n0];
    float2 ch = *(float2*)&csm[s_hi*NP + n0];
    float cold[4] = {cl.x, cl.y, ch.x, ch.y};
    float2 nl, nh;
    #pragma unroll
    for (int r = 0; r < 4; r++){
      int half = r >> 1;
      float gi = acc[nt][r], gf = acc[9+nt][r], gz = acc[18+nt][r], go = acc[27+nt][r];
      float cn = sig_a(gf)*cold[r] + sig_a(gi)*tanh_a(gz);
      if (r == 0) nl.x = cn; else if (r == 1) nl.y = cn;
      else if (r == 2) nh.x = cn; else nh.y = cn;
      float h = sig_a(go)*tanh_a(cn);
      int n = n0 + (r & 1);
      int lane = ((n & 7) << 2) + (T >> 1);
      int ui = ((ks*9 + nt)*32 + lane)*2 + half;
      ((unsigned short*)&XH[ui])[T & 1] = hfbits(h);
    }
    *(float2*)&csm[s_lo*NP + n0] = nl;
    *(float2*)&csm[s_hi*NP + n0] = nh;
  }
}

__device__ __forceinline__ void stage_seq(const float* __restrict__ seq, int base, int t,
                                          uint32_t* XH, int tid){
  for (int idx = tid; idx < NP*S_SEQ; idx += THREADS){
    int nl = idx >> 5, i = idx & 31;
    int a = base + nl; if (a >= N_NODES) a = N_NODES - 1;
    float v = seq[(size_t)a*(T_SEQ*S_SEQ) + t*S_SEQ + i];
    int ks = 16 + (i >> 4), kl = i & 15;
    int r = kl >> 3, cq = (kl & 7) >> 1, hf = kl & 1;
    int lane = ((nl & 7) << 2) + cq;
    int nt = nl >> 3;
    int ui = ((ks*9 + nt)*32 + lane)*2 + r;
    ((unsigned short*)&XH[ui])[hf] = hfbits(v);
  }
}

__global__ void __launch_bounds__(THREADS)
k_mega(const float* __restrict__ seq, const float* __restrict__ bih1,
       const float* __restrict__ bhh1, const float* __restrict__ fcw,
       const float* __restrict__ fcb, float* __restrict__ out){
  extern __shared__ uint32_t smu[];
  uint32_t* XH = smu;
  float* c0 = (float*)(smu + XF_U);
  float* c1 = c0 + 9216;
  uint4* W0S   = (uint4*)(smu + ZERO_U);
  uint4* Wring = W0S + W0S_U4;
  int tid = threadIdx.x, w = tid >> 5, l = tid & 31;
  int blk = blockIdx.x, base = blk*NP;
  int T = l >> 2, o = w*32 + l;
  uint32_t ring_addr;
  asm("{ .reg .u64 t; cvta.to.shared.u64 t, %1; cvt.u32.u64 %0, t; }"
      : "=r"(ring_addr) : "l"((const void*)Wring));

  for (int i = tid; i < ZERO_U; i += THREADS) smu[i] = 0;
  for (int i = tid; i < W0S_U4; i += THREADS) W0S[i] = g_WF[i];  // static chunks 0..2
  __syncthreads();
  stage_seq(seq, base, 0, XH, tid);

  float b1v[4][2];
  #pragma unroll
  for (int g = 0; g < 4; g++)
    #pragma unroll
    for (int hf = 0; hf < 2; hf++){
      int m = g*128 + w*16 + T + 8*hf;
      b1v[g][hf] = __ldg(&bih1[m]) + __ldg(&bhh1[m]);
    }
  __syncthreads();

  // ---- cp.async pipeline prologue: chunks p=0,1 in flight; a_cur <- p=0 ----
  uint4 a_cur[4];
  int sA = 0, pA = 0;
  cp_issue(ring_addr, 0, 0, o);
  cp_issue(ring_addr, 1, 1, o);
  asm volatile("cp.async.wait_group 1;" ::: "memory");
  ld_frags(a_cur, Wring, o);

  const float4* gp = g_gpF + (blk*8 + w)*1152;

  for (int t = 0; t < T_SEQ; t++){
    // ================= phase A: gemm0 (ks 8..17) =================
    float acc0[36][4];
    #pragma unroll
    for (int g = 0; g < 4; g++)
      #pragma unroll
      for (int nt = 0; nt < 9; nt++){
        float4 v = __ldg(&gp[g*288 + nt*32 + l]);
        acc0[g*9+nt][0] = v.x; acc0[g*9+nt][1] = v.y;
        acc0[g*9+nt][2] = v.z; acc0[g*9+nt][3] = v.w;
      }
    {
      uint4 s_cur[4], s_nxt[4];
      ld_frags(s_cur, W0S, o);
      #pragma unroll
      for (int k = 0; k < 3; k++){
        if (k < 2) ld_frags(s_nxt, W0S + (k+1)*1024, o);
        mma_block(XH, s_cur, acc0, 8 + k, l);
        #pragma unroll
        for (int g = 0; g < 4; g++) s_cur[g] = s_nxt[g];
      }
    }
    #pragma unroll 1
    for (int j = 0; j < 7; j++) PIPE_STEP(acc0, 11 + j);
    __syncthreads();

    // ===== phase B: epi0 (MUFU) + stage_seq + gemm1 ks 0..7 (tensor) =====
    // epi0 writes h0 (slots 8..15); gemm1a reads h1 (slots 0..7) — disjoint.
    epilogue(acc0, c0, XH, w, l, 8);
    if (t + 1 < T_SEQ) stage_seq(seq, base, t + 1, XH, tid);
    float acc1[36][4];
    #pragma unroll
    for (int g = 0; g < 4; g++)
      #pragma unroll
      for (int nt = 0; nt < 9; nt++){
        acc1[g*9+nt][0] = b1v[g][0]; acc1[g*9+nt][1] = b1v[g][0];
        acc1[g*9+nt][2] = b1v[g][1]; acc1[g*9+nt][3] = b1v[g][1];
      }
    #pragma unroll 1
    for (int j = 0; j < 8; j++) PIPE_STEP(acc1, j);
    __syncthreads();

    // ===== phase C: gemm1 ks 8..15 (reads h0 from epi0) + epi1 =====
    #pragma unroll 1
    for (int j = 8; j < 16; j++) PIPE_STEP(acc1, j);
    // epi1 needs only thread-local acc1; writes h1 (slots 0..7), read next step
    // phase B (two syncs away). Warp skew overlaps this MUFU with other warps' mma.
    epilogue(acc1, c1, XH, w, l, 0);
    __syncthreads();
  }
  asm volatile("cp.async.wait_group 0;" ::: "memory");

  if (tid < NP){
    int a = base + tid;
    if (a < N_NODES){
      float sum = __ldg(fcb);
      int nt = tid >> 3, lanebase = (tid & 7) << 2;
      #pragma unroll 8
      for (int s = 0; s < H; s++){
        int ks = s >> 4, kl = s & 15, r = kl >> 3, cq = (kl & 7) >> 1, hf = kl & 1;
        int ui = ((ks*9 + nt)*32 + lanebase + cq)*2 + r;
        sum += hf2f(((unsigned short*)&XH[ui])[hf]) * __ldg(&fcw[s]);
      }
      out[a] = sum;
    }
  }
}

// ---------------- launch ----------------
extern "C" void kernel_launch(void* const* d_in, const int* in_sizes, int n_in,
                              void* d_out, int out_size){
  const float* seq  = (const float*)d_in[0];
  const void*  ei   = d_in[1];
  const float* nf   = (const float*)d_in[3];
  const float* gw   = (const float*)d_in[5];
  const float* gb   = (const float*)d_in[6];
  const float* wih0 = (const float*)d_in[7];
  const float* whh0 = (const float*)d_in[8];
  const float* bih0 = (const float*)d_in[9];
  const float* bhh0 = (const float*)d_in[10];
  const float* wih1 = (const float*)d_in[11];
  const float* whh1 = (const float*)d_in[12];
  const float* bih1 = (const float*)d_in[13];
  const float* bhh1 = (const float*)d_in[14];
  const float* fcw  = (const float*)d_in[15];
  const float* fcb  = (const float*)d_in[16];
  float* out = (float*)d_out;

  k_reset<<<1,1>>>();
  k_detect<<<64,256>>>((const int*)ei);
  k_init<<<(N_NODES*C_GCN + 255)/256, 256>>>();
  k_degedge<<<(N_EDGES + 255)/256, 256>>>(ei);
  k_xw<<<(N_NODES*C_GCN + 255)/256, 256>>>(nf, gw);
  k_scatter<<<(N_EDGES*64 + 255)/256, 256>>>(ei);
  k_gcnT<<<(N_NODES*C_GCN + 255)/256, 256>>>(gb);
  k_gpf<<<(512*NPAD + 255)/256, 256>>>(wih0, bih0, bhh0);
  k_wf<<<(106496 + 255)/256, 256>>>(wih0, whh0, wih1, whh1);

  cudaFuncSetAttribute(k_mega, cudaFuncAttributeMaxDynamicSharedMemorySize, SMEM_B);
  k_mega<<<NBLK, THREADS, SMEM_B>>>(seq, bih1, bhh1, fcw, fcb, out);
}

// round 12
// speedup vs baseline: 1.3289x; 1.0328x over previous
#include <cuda_runtime.h>
#include <cuda_fp16.h>
#include <cstdint>

#define N_NODES 10000
#define N_EDGES 160000
#define F_NODE  128
#define C_GCN   64
#define S_SEQ   32
#define T_SEQ   96
#define H       128
#define NP      72
#define NBLK    148
#define NPAD    (NBLK*NP)      /* 10656 */
#define THREADS 256

#define XF_U    10368          /* 18 kslots x 9 ntiles x 32 lanes x 2 u32 */
#define ZERO_U  (XF_U + 2*9216)            /* XH + c0 + c1 = 28800 u32 */
#define W0S_U4  3072                       /* 3 static k16 chunks */
#define RING_U4 3072                       /* 3-slot cp.async ring */
#define SMEM_B  ((ZERO_U + (W0S_U4 + RING_U4)*4)*4)   /* 213504 B */

// ---------------- device globals ----------------
__device__ int    g_i32;
__device__ float  g_deg [N_NODES];
__device__ float  g_xwS [N_NODES*C_GCN];
__device__ float  g_acc [N_NODES*C_GCN];
__device__ float  g_gcnT[C_GCN*N_NODES];
__device__ float4 g_gpF [NBLK*8*4*9*32];   // [blk][w][g][nt][lane] d-frag f32x4
__device__ uint4  g_WF  [26624];           // fp16 A-frags: layer0 10240, layer1 16384

__device__ __forceinline__ int eidx(const void* ei, int idx){
  if (g_i32) return ((const int*)ei)[idx];
  return (int)((const long long*)ei)[idx];
}

// ---------------- GCN prep ----------------
__global__ void k_reset(){ g_i32 = 0; }

// fused: zero acc, init deg, and detect int32-vs-int64 edge dtype
__global__ void k_init(const int* ei){
  int i = blockIdx.x*blockDim.x + threadIdx.x;
  if (i < N_NODES*C_GCN){
    g_acc[i] = 0.f;
    if (i < N_NODES) g_deg[i] = 1.f;
  }
  int any = 0;
  for (int e = i; e < N_EDGES; e += gridDim.x*blockDim.x) any |= ei[2*e+1];
  if (__syncthreads_or(any)) { if (threadIdx.x == 0) atomicOr(&g_i32, 1); }
}

__global__ void k_degedge(const void* ei){
  int e = blockIdx.x*blockDim.x + threadIdx.x;
  if (e < N_EDGES) atomicAdd(&g_deg[eidx(ei, N_EDGES + e)], 1.f);
}

__global__ void k_xw(const float* __restrict__ nf, const float* __restrict__ gw){
  int idx = blockIdx.x*blockDim.x + threadIdx.x;
  if (idx >= N_NODES*C_GCN) return;
  int n = idx >> 6, c = idx & 63;
  float s = 0.f;
  #pragma unroll 8
  for (int k = 0; k < F_NODE; k++) s += nf[n*F_NODE + k] * __ldg(&gw[k*C_GCN + c]);
  g_xwS[idx] = s * rsqrtf(g_deg[n]);
}

__global__ void k_scatter(const void* ei){
  int idx = blockIdx.x*blockDim.x + threadIdx.x;
  if (idx >= N_EDGES*64) return;
  int e = idx >> 6, c = idx & 63;
  atomicAdd(&g_acc[eidx(ei, N_EDGES + e)*64 + c], g_xwS[eidx(ei, e)*64 + c]);
}

__global__ void k_gcnT(const float* __restrict__ gb){
  int idx = blockIdx.x*blockDim.x + threadIdx.x;
  if (idx >= N_NODES*C_GCN) return;
  int n = idx >> 6, c = idx & 63;
  float v = rsqrtf(g_deg[n]) * (g_acc[idx] + g_xwS[idx]) + __ldg(&gb[c]);
  g_gcnT[c*N_NODES + n] = v;
}

// gpart (gcn + both layer-0 biases) baked into D-fragment layout.
// One warp handles 32 consecutive nodes x one 32-row m-group; gcnT lives in
// registers (64/thread), wih0 reads are warp-uniform (L1 broadcast).
__global__ void k_gpf(const float* __restrict__ wih0, const float* __restrict__ bih0,
                      const float* __restrict__ bhh0){
  int gt = blockIdx.x*blockDim.x + threadIdx.x;
  int warp = gt >> 5, lane = gt & 31;
  int mg = warp & 15;          // m-group of 32 rows
  int pw = warp >> 4;          // node-group of 32
  int p = pw*32 + lane;
  if (p >= NPAD) return;
  int a = p < N_NODES ? p : N_NODES - 1;
  float gc[64];
  #pragma unroll
  for (int j = 0; j < 64; j++) gc[j] = g_gcnT[j*N_NODES + a];
  int blk = p / NP, pl = p - blk*NP;
  int nt = pl >> 3, n8 = pl & 7, cq = n8 >> 1, dn = n8 & 1;
  #pragma unroll 1
  for (int mi = 0; mi < 32; mi++){
    int m = mg*32 + mi;
    float s = __ldg(&bih0[m]) + __ldg(&bhh0[m]);
    #pragma unroll
    for (int j = 0; j < 64; j++) s += gc[j] * __ldg(&wih0[m*96 + 32 + j]);
    int g = m >> 7, ml = m & 127, w = ml >> 4, t8 = ml & 15, T = t8 & 7, hf = t8 >> 3;
    int lane2 = T*4 + cq, r = hf*2 + dn;
    ((float*)g_gpF)[((((blk*8 + w)*4 + g)*9 + nt)*32 + lane2)*4 + r] = s;
  }
}

__device__ __forceinline__ unsigned short hfbits(float v){
  __half h = __float2half_rn(v);
  return *(unsigned short*)&h;
}
__device__ __forceinline__ float hf2f(unsigned short u){
  return __half2float(*(__half*)&u);
}

// Weights pre-permuted into mma A-fragment order, single fp16.
// idx = [k16][g][w][lane][reg]; layer = (k16 >= 10)
__global__ void k_wf(const float* __restrict__ wih0, const float* __restrict__ whh0,
                     const float* __restrict__ wih1, const float* __restrict__ whh1){
  int idx = blockIdx.x*blockDim.x + threadIdx.x;
  if (idx >= 106496) return;
  int reg = idx & 3, l = (idx >> 2) & 31;
  int w = (idx >> 7) & 7, g = (idx >> 10) & 3, k16 = idx >> 12;
  int layer = (k16 >= 10);
  int k16l = layer ? k16 - 10 : k16;
  int T = l >> 2, cq = l & 3;
  int row  = T + 8*(reg & 1);
  int colb = 2*cq + 8*(reg >> 1);
  int m = g*128 + w*16 + row;
  int k = k16l*16 + colb;                 // k even; pair never straddles 128
  float v0, v1;
  if (layer){
    if (k < 128){ v0 = whh1[m*128 + k];       v1 = whh1[m*128 + k + 1]; }
    else        { v0 = wih1[m*128 + k - 128]; v1 = wih1[m*128 + k - 127]; }
  } else {
    if (k < 128){ v0 = whh0[m*128 + k];       v1 = whh0[m*128 + k + 1]; }
    else        { v0 = wih0[m*96 + k - 128];  v1 = wih0[m*96 + k - 127]; }
  }
  ((uint32_t*)g_WF)[idx] = ((uint32_t)hfbits(v1) << 16) | (uint32_t)hfbits(v0);
}

// ---------------- mega kernel ----------------
__device__ __forceinline__ float tanh_a(float x){
  float r; asm("tanh.approx.f32 %0, %1;" : "=f"(r) : "f"(x)); return r;
}
__device__ __forceinline__ float sig_a(float x){
  return fmaf(0.5f, tanh_a(0.5f*x), 0.5f);
}

__device__ __forceinline__ void mma_f16(float* d, const uint32_t* a, uint2 b){
  asm volatile("mma.sync.aligned.m16n8k16.row.col.f32.f16.f16.f32 "
               "{%0,%1,%2,%3}, {%4,%5,%6,%7}, {%8,%9}, {%0,%1,%2,%3};"
               : "+f"(d[0]), "+f"(d[1]), "+f"(d[2]), "+f"(d[3])
               : "r"(a[0]), "r"(a[1]), "r"(a[2]), "r"(a[3]), "r"(b.x), "r"(b.y));
}

// one k16 chunk against all 9 n-tiles and 4 gates
__device__ __forceinline__ void mma_block(const uint32_t* __restrict__ XH,
                                          const uint4 a[4], float acc[36][4],
                                          int ks, int l){
  #pragma unroll
  for (int nt = 0; nt < 9; nt++){
    uint2 bh = *(const uint2*)&XH[((ks*9 + nt)*32 + l)*2];
    #pragma unroll
    for (int g = 0; g < 4; g++)
      mma_f16(acc[g*9+nt], (const uint32_t*)&a[g], bh);
  }
}

__device__ __forceinline__ void ld_frags(uint4 a[4], const uint4* __restrict__ base, int o){
  #pragma unroll
  for (int g = 0; g < 4; g++) a[g] = base[g*256 + o];
}

// issue one k16 chunk into the ring; streamed ids per step are p+3 (p in 0..22)
__device__ __forceinline__ void cp_issue(uint32_t ring_addr, int slot, int p, int o){
  const char* src = (const char*)(g_WF + (p + 3)*1024 + o);
  uint32_t dst = ring_addr + (uint32_t)(slot*16384 + o*16);
  #pragma unroll
  for (int g = 0; g < 4; g++){
    asm volatile("{ .reg .u64 gp; cvta.to.global.u64 gp, %1;"
                 " cp.async.cg.shared.global [%0], [gp], 16; }"
                 :: "r"(dst + g*4096), "l"(src + (size_t)g*4096) : "memory");
  }
  asm volatile("cp.async.commit_group;" ::: "memory");
}

#define PIPE_STEP(ACC, KS) do { \
  int sI = sA + 2; if (sI >= 3) sI -= 3; \
  int pI = pA + 2; if (pI >= 23) pI -= 23; \
  cp_issue(ring_addr, sI, pI, o); \
  mma_block(XH, a_cur, (ACC), (KS), l); \
  asm volatile("cp.async.wait_group 1;" ::: "memory"); \
  sA = (sA + 1 == 3) ? 0 : sA + 1; \
  pA = (pA + 1 == 23) ? 0 : pA + 1; \
  ld_frags(a_cur, Wring + sA*1024, o); \
} while(0)

__device__ __forceinline__ void epilogue(float acc[36][4], float* csm,
                                         uint32_t* XH, int w, int l, int ksbase){
  int T = l >> 2, cq = l & 3;
  int ks = ksbase + w;
  int s_lo = w*16 + T, s_hi = s_lo + 8;
  #pragma unroll
  for (int nt = 0; nt < 9; nt++){
    int n0 = nt*8 + 2*cq;
    float2 cl = *(float2*)&csm[s_lo*NP + n0];
    float2 ch = *(float2*)&csm[s_hi*NP + n0];
    float cold[4] = {cl.x, cl.y, ch.x, ch.y};
    float2 nl, nh;
    #pragma unroll
    for (int r = 0; r < 4; r++){
      int half = r >> 1;
      float gi = acc[nt][r], gf = acc[9+nt][r], gz = acc[18+nt][r], go = acc[27+nt][r];
      float cn = sig_a(gf)*cold[r] + sig_a(gi)*tanh_a(gz);
      if (r == 0) nl.x = cn; else if (r == 1) nl.y = cn;
      else if (r == 2) nh.x = cn; else nh.y = cn;
      float h = sig_a(go)*tanh_a(cn);
      int n = n0 + (r & 1);
      int lane = ((n & 7) << 2) + (T >> 1);
      int ui = ((ks*9 + nt)*32 + lane)*2 + half;
      ((unsigned short*)&XH[ui])[T & 1] = hfbits(h);
    }
    *(float2*)&csm[s_lo*NP + n0] = nl;
    *(float2*)&csm[s_hi*NP + n0] = nh;
  }
}

__device__ __forceinline__ void stage_seq(const float* __restrict__ seq, int base, int t,
                                          uint32_t* XH, int tid){
  for (int idx = tid; idx < NP*S_SEQ; idx += THREADS){
    int nl = idx >> 5, i = idx & 31;
    int a = base + nl; if (a >= N_NODES) a = N_NODES - 1;
    float v = seq[(size_t)a*(T_SEQ*S_SEQ) + t*S_SEQ + i];
    int ks = 16 + (i >> 4), kl = i & 15;
    int r = kl >> 3, cq = (kl & 7) >> 1, hf = kl & 1;
    int lane = ((nl & 7) << 2) + cq;
    int nt = nl >> 3;
    int ui = ((ks*9 + nt)*32 + lane)*2 + r;
    ((unsigned short*)&XH[ui])[hf] = hfbits(v);
  }
}

__global__ void __launch_bounds__(THREADS)
k_mega(const float* __restrict__ seq, const float* __restrict__ bih1,
       const float* __restrict__ bhh1, const float* __restrict__ fcw,
       const float* __restrict__ fcb, float* __restrict__ out){
  extern __shared__ uint32_t smu[];
  uint32_t* XH = smu;
  float* c0 = (float*)(smu + XF_U);
  float* c1 = c0 + 9216;
  uint4* W0S   = (uint4*)(smu + ZERO_U);
  uint4* Wring = W0S + W0S_U4;
  int tid = threadIdx.x, w = tid >> 5, l = tid & 31;
  int blk = blockIdx.x, base = blk*NP;
  int T = l >> 2, o = w*32 + l;
  uint32_t ring_addr;
  asm("{ .reg .u64 t; cvta.to.shared.u64 t, %1; cvt.u32.u64 %0, t; }"
      : "=r"(ring_addr) : "l"((const void*)Wring));

  for (int i = tid; i < ZERO_U; i += THREADS) smu[i] = 0;
  for (int i = tid; i < W0S_U4; i += THREADS) W0S[i] = g_WF[i];  // static chunks 0..2
  __syncthreads();
  stage_seq(seq, base, 0, XH, tid);

  float b1v[4][2];
  #pragma unroll
  for (int g = 0; g < 4; g++)
    #pragma unroll
    for (int hf = 0; hf < 2; hf++){
      int m = g*128 + w*16 + T + 8*hf;
      b1v[g][hf] = __ldg(&bih1[m]) + __ldg(&bhh1[m]);
    }
  __syncthreads();

  // ---- cp.async pipeline prologue: chunks p=0,1 in flight; a_cur <- p=0 ----
  uint4 a_cur[4];
  int sA = 0, pA = 0;
  cp_issue(ring_addr, 0, 0, o);
  cp_issue(ring_addr, 1, 1, o);
  asm volatile("cp.async.wait_group 1;" ::: "memory");
  ld_frags(a_cur, Wring, o);

  const float4* gp = g_gpF + (blk*8 + w)*1152;

  for (int t = 0; t < T_SEQ; t++){
    // ================= phase A: gemm0 (ks 8..17) =================
    // (no barrier between prior epi1 and here: epi1 writes slots 0..7/c1,
    //  phase A reads gpF + slots 8..17 only — disjoint. First reader of
    //  slots 0..7 is phase B, one barrier away.)
    float acc0[36][4];
    #pragma unroll
    for (int g = 0; g < 4; g++)
      #pragma unroll
      for (int nt = 0; nt < 9; nt++){
        float4 v = __ldg(&gp[g*288 + nt*32 + l]);
        acc0[g*9+nt][0] = v.x; acc0[g*9+nt][1] = v.y;
        acc0[g*9+nt][2] = v.z; acc0[g*9+nt][3] = v.w;
      }
    {
      uint4 s_cur[4], s_nxt[4];
      ld_frags(s_cur, W0S, o);
      #pragma unroll
      for (int k = 0; k < 3; k++){
        if (k < 2) ld_frags(s_nxt, W0S + (k+1)*1024, o);
        mma_block(XH, s_cur, acc0, 8 + k, l);
        #pragma unroll
        for (int g = 0; g < 4; g++) s_cur[g] = s_nxt[g];
      }
    }
    #pragma unroll 1
    for (int j = 0; j < 7; j++) PIPE_STEP(acc0, 11 + j);
    __syncthreads();

    // ===== phase B: epi0 (MUFU) + stage_seq + gemm1 ks 0..7 (tensor) =====
    // epi0 writes h0 (slots 8..15); gemm1a reads h1 (slots 0..7) — disjoint.
    epilogue(acc0, c0, XH, w, l, 8);
    if (t + 1 < T_SEQ) stage_seq(seq, base, t + 1, XH, tid);
    float acc1[36][4];
    #pragma unroll
    for (int g = 0; g < 4; g++)
      #pragma unroll
      for (int nt = 0; nt < 9; nt++){
        acc1[g*9+nt][0] = b1v[g][0]; acc1[g*9+nt][1] = b1v[g][0];
        acc1[g*9+nt][2] = b1v[g][1]; acc1[g*9+nt][3] = b1v[g][1];
      }
    #pragma unroll 1
    for (int j = 0; j < 8; j++) PIPE_STEP(acc1, j);
    __syncthreads();

    // ===== phase C: gemm1 ks 8..15 (reads h0 from epi0) + epi1 =====
    #pragma unroll 1
    for (int j = 8; j < 16; j++) PIPE_STEP(acc1, j);
    // epi1 is thread-local in acc1; its MUFU tail overlaps the next phase A's
    // acc-init LDGs and mma stream across warps (no barrier here).
    epilogue(acc1, c1, XH, w, l, 0);
  }
  asm volatile("cp.async.wait_group 0;" ::: "memory");
  __syncthreads();   // make final epi1 h1 writes visible to the FC below

  if (tid < NP){
    int a = base + tid;
    if (a < N_NODES){
      float sum = __ldg(fcb);
      int nt = tid >> 3, lanebase = (tid & 7) << 2;
      #pragma unroll 8
      for (int s = 0; s < H; s++){
        int ks = s >> 4, kl = s & 15, r = kl >> 3, cq = (kl & 7) >> 1, hf = kl & 1;
        int ui = ((ks*9 + nt)*32 + lanebase + cq)*2 + r;
        sum += hf2f(((unsigned short*)&XH[ui])[hf]) * __ldg(&fcw[s]);
      }
      out[a] = sum;
    }
  }
}

// ---------------- launch ----------------
extern "C" void kernel_launch(void* const* d_in, const int* in_sizes, int n_in,
                              void* d_out, int out_size){
  const float* seq  = (const float*)d_in[0];
  const void*  ei   = d_in[1];
  const float* nf   = (const float*)d_in[3];
  const float* gw   = (const float*)d_in[5];
  const float* gb   = (const float*)d_in[6];
  const float* wih0 = (const float*)d_in[7];
  const float* whh0 = (const float*)d_in[8];
  const float* bih0 = (const float*)d_in[9];
  const float* bhh0 = (const float*)d_in[10];
  const float* wih1 = (const float*)d_in[11];
  const float* whh1 = (const float*)d_in[12];
  const float* bih1 = (const float*)d_in[13];
  const float* bhh1 = (const float*)d_in[14];
  const float* fcw  = (const float*)d_in[15];
  const float* fcb  = (const float*)d_in[16];
  float* out = (float*)d_out;

  k_reset<<<1,1>>>();
  k_init<<<(N_NODES*C_GCN + 255)/256, 256>>>((const int*)ei);
  k_degedge<<<(N_EDGES + 255)/256, 256>>>(ei);
  k_xw<<<(N_NODES*C_GCN + 255)/256, 256>>>(nf, gw);
  k_scatter<<<(N_EDGES*64 + 255)/256, 256>>>(ei);
  k_gcnT<<<(N_NODES*C_GCN + 255)/256, 256>>>(gb);
  k_gpf<<<666, 256>>>(wih0, bih0, bhh0);
  k_wf<<<(106496 + 255)/256, 256>>>(wih0, whh0, wih1, whh1);

  cudaFuncSetAttribute(k_mega, cudaFuncAttributeMaxDynamicSharedMemorySize, SMEM_B);
  k_mega<<<NBLK, THREADS, SMEM_B>>>(seq, bih1, bhh1, fcw, fcb, out);
}

// round 13
// speedup vs baseline: 1.3347x; 1.0044x over previous
#include <cuda_runtime.h>
#include <cuda_fp16.h>
#include <cstdint>

#define N_NODES 10000
#define N_EDGES 160000
#define F_NODE  128
#define C_GCN   64
#define S_SEQ   32
#define T_SEQ   96
#define H       128
#define NP      72
#define NBLK    148
#define NPAD    (NBLK*NP)      /* 10656 */
#define THREADS 256

#define XF_U    10368          /* 18 kslots x 9 ntiles x 32 lanes x 2 u32 */
#define ZERO_U  (XF_U + 2*9216)            /* XH + c0 + c1 = 28800 u32 */
#define W0S_U4  3072                       /* 3 static k16 chunks */
#define RING_U4 3072                       /* 3-slot cp.async ring */
#define SMEM_B  ((ZERO_U + (W0S_U4 + RING_U4)*4)*4)   /* 213504 B */

// ---------------- device globals ----------------
__device__ int    g_i32;
__device__ float  g_deg [N_NODES];
__device__ float  g_xwS [N_NODES*C_GCN];
__device__ int    g_off [N_NODES];
__device__ int    g_fill[N_NODES];
__device__ int    g_src [N_EDGES];
__device__ float  g_gcnT[C_GCN*N_NODES];
__device__ float4 g_gpF [NBLK*8*4*9*32];   // [blk][w][g][nt][lane] d-frag f32x4
__device__ uint4  g_WF  [26624];           // fp16 A-frags: layer0 10240, layer1 16384

__device__ __forceinline__ int eidx(const void* ei, int idx){
  if (g_i32) return ((const int*)ei)[idx];
  return (int)((const long long*)ei)[idx];
}

// ---------------- GCN prep ----------------
__global__ void k_reset(){ g_i32 = 0; }

// fused: init deg, zero fill counters, detect int32-vs-int64 edge dtype
__global__ void k_init(const int* ei){
  int i = blockIdx.x*blockDim.x + threadIdx.x;
  if (i < N_NODES){ g_deg[i] = 1.f; g_fill[i] = 0; }
  int any = 0;
  for (int e = i; e < N_EDGES; e += gridDim.x*blockDim.x) any |= ei[2*e+1];
  if (__syncthreads_or(any)) { if (threadIdx.x == 0) atomicOr(&g_i32, 1); }
}

__global__ void k_degedge(const void* ei){
  int e = blockIdx.x*blockDim.x + threadIdx.x;
  if (e < N_EDGES) atomicAdd(&g_deg[eidx(ei, N_EDGES + e)], 1.f);
}

// exclusive prefix sum of (deg-1) -> g_off ; single block of 1024
__global__ void k_scan(){
  __shared__ int part[1024];
  int tid = threadIdx.x;
  int base = tid*10;
  int v[10], s = 0;
  #pragma unroll
  for (int i = 0; i < 10; i++){
    int n = base + i;
    int c = (n < N_NODES) ? ((int)g_deg[n] - 1) : 0;
    v[i] = s; s += c;
  }
  part[tid] = s;
  __syncthreads();
  for (int d = 1; d < 1024; d <<= 1){
    int x = (tid >= d) ? part[tid-d] : 0;
    __syncthreads();
    part[tid] += x;
    __syncthreads();
  }
  int add = (tid > 0) ? part[tid-1] : 0;
  #pragma unroll
  for (int i = 0; i < 10; i++){
    int n = base + i;
    if (n < N_NODES) g_off[n] = add + v[i];
  }
}

// counting-sort edge sources by destination node
__global__ void k_place(const void* ei){
  int e = blockIdx.x*blockDim.x + threadIdx.x;
  if (e >= N_EDGES) return;
  int col = eidx(ei, N_EDGES + e);
  int pos = atomicAdd(&g_fill[col], 1);
  g_src[g_off[col] + pos] = eidx(ei, e);
}

// xw = (nf @ gw) * dinv[n]; gw cached in smem, thread = (node, c-quad)
__global__ void k_xw(const float* __restrict__ nf, const float* __restrict__ gw){
  __shared__ float gws[F_NODE*C_GCN];
  int tid = threadIdx.x;
  for (int i = tid; i < F_NODE*C_GCN/4; i += 256)
    ((float4*)gws)[i] = ((const float4*)gw)[i];
  __syncthreads();
  int q = tid & 15, nl = tid >> 4;
  int n = blockIdx.x*16 + nl;
  if (n >= N_NODES) return;
  float4 acc = {0.f, 0.f, 0.f, 0.f};
  const float4* nfr = (const float4*)(nf + (size_t)n*F_NODE);
  #pragma unroll 4
  for (int k4 = 0; k4 < 32; k4++){
    float4 a = nfr[k4];
    #pragma unroll
    for (int kk = 0; kk < 4; kk++){
      float av = (kk==0)?a.x:(kk==1)?a.y:(kk==2)?a.z:a.w;
      const float* gr = &gws[(k4*4 + kk)*C_GCN + q*4];
      acc.x += av*gr[0]; acc.y += av*gr[1]; acc.z += av*gr[2]; acc.w += av*gr[3];
    }
  }
  float r = rsqrtf(g_deg[n]);
  acc.x *= r; acc.y *= r; acc.z *= r; acc.w *= r;
  *(float4*)&g_xwS[n*C_GCN + q*4] = acc;
}

// gather-sum incoming messages + self loop, normalize, add bias -> gcnT
__global__ void k_gather(const float* __restrict__ gb){
  int tid = threadIdx.x;
  int c = tid & 63, nl = tid >> 6;
  int n = blockIdx.x*4 + nl;
  if (n >= N_NODES) return;
  int off = g_off[n];
  int cnt = (int)g_deg[n] - 1;
  float s = g_xwS[n*C_GCN + c];
  for (int j = 0; j < cnt; j++)
    s += g_xwS[g_src[off + j]*C_GCN + c];
  g_gcnT[c*N_NODES + n] = rsqrtf(g_deg[n])*s + __ldg(&gb[c]);
}

// gpart (gcn + both layer-0 biases) baked into D-fragment layout.
__global__ void k_gpf(const float* __restrict__ wih0, const float* __restrict__ bih0,
                      const float* __restrict__ bhh0){
  int gt = blockIdx.x*blockDim.x + threadIdx.x;
  int warp = gt >> 5, lane = gt & 31;
  int mg = warp & 15;          // m-group of 32 rows
  int pw = warp >> 4;          // node-group of 32
  int p = pw*32 + lane;
  if (p >= NPAD) return;
  int a = p < N_NODES ? p : N_NODES - 1;
  float gc[64];
  #pragma unroll
  for (int j = 0; j < 64; j++) gc[j] = g_gcnT[j*N_NODES + a];
  int blk = p / NP, pl = p - blk*NP;
  int nt = pl >> 3, n8 = pl & 7, cq = n8 >> 1, dn = n8 & 1;
  #pragma unroll 1
  for (int mi = 0; mi < 32; mi++){
    int m = mg*32 + mi;
    float s = __ldg(&bih0[m]) + __ldg(&bhh0[m]);
    #pragma unroll
    for (int j = 0; j < 64; j++) s += gc[j] * __ldg(&wih0[m*96 + 32 + j]);
    int g = m >> 7, ml = m & 127, w = ml >> 4, t8 = ml & 15, T = t8 & 7, hf = t8 >> 3;
    int lane2 = T*4 + cq, r = hf*2 + dn;
    ((float*)g_gpF)[((((blk*8 + w)*4 + g)*9 + nt)*32 + lane2)*4 + r] = s;
  }
}

__device__ __forceinline__ unsigned short hfbits(float v){
  __half h = __float2half_rn(v);
  return *(unsigned short*)&h;
}
__device__ __forceinline__ float hf2f(unsigned short u){
  return __half2float(*(__half*)&u);
}

// Weights pre-permuted into mma A-fragment order, single fp16.
__global__ void k_wf(const float* __restrict__ wih0, const float* __restrict__ whh0,
                     const float* __restrict__ wih1, const float* __restrict__ whh1){
  int idx = blockIdx.x*blockDim.x + threadIdx.x;
  if (idx >= 106496) return;
  int reg = idx & 3, l = (idx >> 2) & 31;
  int w = (idx >> 7) & 7, g = (idx >> 10) & 3, k16 = idx >> 12;
  int layer = (k16 >= 10);
  int k16l = layer ? k16 - 10 : k16;
  int T = l >> 2, cq = l & 3;
  int row  = T + 8*(reg & 1);
  int colb = 2*cq + 8*(reg >> 1);
  int m = g*128 + w*16 + row;
  int k = k16l*16 + colb;                 // k even; pair never straddles 128
  float v0, v1;
  if (layer){
    if (k < 128){ v0 = whh1[m*128 + k];       v1 = whh1[m*128 + k + 1]; }
    else        { v0 = wih1[m*128 + k - 128]; v1 = wih1[m*128 + k - 127]; }
  } else {
    if (k < 128){ v0 = whh0[m*128 + k];       v1 = whh0[m*128 + k + 1]; }
    else        { v0 = wih0[m*96 + k - 128];  v1 = wih0[m*96 + k - 127]; }
  }
  ((uint32_t*)g_WF)[idx] = ((uint32_t)hfbits(v1) << 16) | (uint32_t)hfbits(v0);
}

// ---------------- mega kernel ----------------
__device__ __forceinline__ float tanh_a(float x){
  float r; asm("tanh.approx.f32 %0, %1;" : "=f"(r) : "f"(x)); return r;
}
__device__ __forceinline__ float sig_a(float x){
  return fmaf(0.5f, tanh_a(0.5f*x), 0.5f);
}

__device__ __forceinline__ void mma_f16(float* d, const uint32_t* a, uint2 b){
  asm volatile("mma.sync.aligned.m16n8k16.row.col.f32.f16.f16.f32 "
               "{%0,%1,%2,%3}, {%4,%5,%6,%7}, {%8,%9}, {%0,%1,%2,%3};"
               : "+f"(d[0]), "+f"(d[1]), "+f"(d[2]), "+f"(d[3])
               : "r"(a[0]), "r"(a[1]), "r"(a[2]), "r"(a[3]), "r"(b.x), "r"(b.y));
}

__device__ __forceinline__ void mma_block(const uint32_t* __restrict__ XH,
                                          const uint4 a[4], float acc[36][4],
                                          int ks, int l){
  #pragma unroll
  for (int nt = 0; nt < 9; nt++){
    uint2 bh = *(const uint2*)&XH[((ks*9 + nt)*32 + l)*2];
    #pragma unroll
    for (int g = 0; g < 4; g++)
      mma_f16(acc[g*9+nt], (const uint32_t*)&a[g], bh);
  }
}

__device__ __forceinline__ void ld_frags(uint4 a[4], const uint4* __restrict__ base, int o){
  #pragma unroll
  for (int g = 0; g < 4; g++) a[g] = base[g*256 + o];
}

__device__ __forceinline__ void cp_issue(uint32_t ring_addr, int slot, int p, int o){
  const char* src = (const char*)(g_WF + (p + 3)*1024 + o);
  uint32_t dst = ring_addr + (uint32_t)(slot*16384 + o*16);
  #pragma unroll
  for (int g = 0; g < 4; g++){
    asm volatile("{ .reg .u64 gp; cvta.to.global.u64 gp, %1;"
                 " cp.async.cg.shared.global [%0], [gp], 16; }"
                 :: "r"(dst + g*4096), "l"(src + (size_t)g*4096) : "memory");
  }
  asm volatile("cp.async.commit_group;" ::: "memory");
}

#define PIPE_STEP(ACC, KS) do { \
  int sI = sA + 2; if (sI >= 3) sI -= 3; \
  int pI = pA + 2; if (pI >= 23) pI -= 23; \
  cp_issue(ring_addr, sI, pI, o); \
  mma_block(XH, a_cur, (ACC), (KS), l); \
  asm volatile("cp.async.wait_group 1;" ::: "memory"); \
  sA = (sA + 1 == 3) ? 0 : sA + 1; \
  pA = (pA + 1 == 23) ? 0 : pA + 1; \
  ld_frags(a_cur, Wring + sA*1024, o); \
} while(0)

__device__ __forceinline__ void epilogue(float acc[36][4], float* csm,
                                         uint32_t* XH, int w, int l, int ksbase){
  int T = l >> 2, cq = l & 3;
  int ks = ksbase + w;
  int s_lo = w*16 + T, s_hi = s_lo + 8;
  #pragma unroll
  for (int nt = 0; nt < 9; nt++){
    int n0 = nt*8 + 2*cq;
    float2 cl = *(float2*)&csm[s_lo*NP + n0];
    float2 ch = *(float2*)&csm[s_hi*NP + n0];
    float cold[4] = {cl.x, cl.y, ch.x, ch.y};
    float2 nl, nh;
    #pragma unroll
    for (int r = 0; r < 4; r++){
      int half = r >> 1;
      float gi = acc[nt][r], gf = acc[9+nt][r], gz = acc[18+nt][r], go = acc[27+nt][r];
      float cn = sig_a(gf)*cold[r] + sig_a(gi)*tanh_a(gz);
      if (r == 0) nl.x = cn; else if (r == 1) nl.y = cn;
      else if (r == 2) nh.x = cn; else nh.y = cn;
      float h = sig_a(go)*tanh_a(cn);
      int n = n0 + (r & 1);
      int lane = ((n & 7) << 2) + (T >> 1);
      int ui = ((ks*9 + nt)*32 + lane)*2 + half;
      ((unsigned short*)&XH[ui])[T & 1] = hfbits(h);
    }
    *(float2*)&csm[s_lo*NP + n0] = nl;
    *(float2*)&csm[s_hi*NP + n0] = nh;
  }
}

__device__ __forceinline__ void stage_seq(const float* __restrict__ seq, int base, int t,
                                          uint32_t* XH, int tid){
  for (int idx = tid; idx < NP*S_SEQ; idx += THREADS){
    int nl = idx >> 5, i = idx & 31;
    int a = base + nl; if (a >= N_NODES) a = N_NODES - 1;
    float v = seq[(size_t)a*(T_SEQ*S_SEQ) + t*S_SEQ + i];
    int ks = 16 + (i >> 4), kl = i & 15;
    int r = kl >> 3, cq = (kl & 7) >> 1, hf = kl & 1;
    int lane = ((nl & 7) << 2) + cq;
    int nt = nl >> 3;
    int ui = ((ks*9 + nt)*32 + lane)*2 + r;
    ((unsigned short*)&XH[ui])[hf] = hfbits(v);
  }
}

__global__ void __launch_bounds__(THREADS)
k_mega(const float* __restrict__ seq, const float* __restrict__ bih1,
       const float* __restrict__ bhh1, const float* __restrict__ fcw,
       const float* __restrict__ fcb, float* __restrict__ out){
  extern __shared__ uint32_t smu[];
  uint32_t* XH = smu;
  float* c0 = (float*)(smu + XF_U);
  float* c1 = c0 + 9216;
  uint4* W0S   = (uint4*)(smu + ZERO_U);
  uint4* Wring = W0S + W0S_U4;
  int tid = threadIdx.x, w = tid >> 5, l = tid & 31;
  int blk = blockIdx.x, base = blk*NP;
  int T = l >> 2, o = w*32 + l;
  uint32_t ring_addr;
  asm("{ .reg .u64 t; cvta.to.shared.u64 t, %1; cvt.u32.u64 %0, t; }"
      : "=r"(ring_addr) : "l"((const void*)Wring));

  for (int i = tid; i < ZERO_U; i += THREADS) smu[i] = 0;
  for (int i = tid; i < W0S_U4; i += THREADS) W0S[i] = g_WF[i];  // static chunks 0..2
  __syncthreads();
  stage_seq(seq, base, 0, XH, tid);

  float b1v[4][2];
  #pragma unroll
  for (int g = 0; g < 4; g++)
    #pragma unroll
    for (int hf = 0; hf < 2; hf++){
      int m = g*128 + w*16 + T + 8*hf;
      b1v[g][hf] = __ldg(&bih1[m]) + __ldg(&bhh1[m]);
    }
  __syncthreads();

  // ---- cp.async pipeline prologue ----
  uint4 a_cur[4];
  int sA = 0, pA = 0;
  cp_issue(ring_addr, 0, 0, o);
  cp_issue(ring_addr, 1, 1, o);
  asm volatile("cp.async.wait_group 1;" ::: "memory");
  ld_frags(a_cur, Wring, o);

  const float4* gp = g_gpF + (blk*8 + w)*1152;

  for (int t = 0; t < T_SEQ; t++){
    // ================= phase A: gemm0 (ks 8..17) =================
    float acc0[36][4];
    #pragma unroll
    for (int g = 0; g < 4; g++)
      #pragma unroll
      for (int nt = 0; nt < 9; nt++){
        float4 v = __ldg(&gp[g*288 + nt*32 + l]);
        acc0[g*9+nt][0] = v.x; acc0[g*9+nt][1] = v.y;
        acc0[g*9+nt][2] = v.z; acc0[g*9+nt][3] = v.w;
      }
    {
      uint4 s_cur[4], s_nxt[4];
      ld_frags(s_cur, W0S, o);
      #pragma unroll
      for (int k = 0; k < 3; k++){
        if (k < 2) ld_frags(s_nxt, W0S + (k+1)*1024, o);
        mma_block(XH, s_cur, acc0, 8 + k, l);
        #pragma unroll
        for (int g = 0; g < 4; g++) s_cur[g] = s_nxt[g];
      }
    }
    #pragma unroll 1
    for (int j = 0; j < 7; j++) PIPE_STEP(acc0, 11 + j);
    __syncthreads();

    // ===== phase B: epi0 + stage_seq + gemm1 ks 0..7 =====
    epilogue(acc0, c0, XH, w, l, 8);
    if (t + 1 < T_SEQ) stage_seq(seq, base, t + 1, XH, tid);
    float acc1[36][4];
    #pragma unroll
    for (int g = 0; g < 4; g++)
      #pragma unroll
      for (int nt = 0; nt < 9; nt++){
        acc1[g*9+nt][0] = b1v[g][0]; acc1[g*9+nt][1] = b1v[g][0];
        acc1[g*9+nt][2] = b1v[g][1]; acc1[g*9+nt][3] = b1v[g][1];
      }
    #pragma unroll 1
    for (int j = 0; j < 8; j++) PIPE_STEP(acc1, j);
    __syncthreads();

    // ===== phase C: gemm1 ks 8..15 + epi1 (no trailing barrier) =====
    #pragma unroll 1
    for (int j = 8; j < 16; j++) PIPE_STEP(acc1, j);
    epilogue(acc1, c1, XH, w, l, 0);
  }
  asm volatile("cp.async.wait_group 0;" ::: "memory");
  __syncthreads();   // make final epi1 h1 writes visible to the FC below

  if (tid < NP){
    int a = base + tid;
    if (a < N_NODES){
      float sum = __ldg(fcb);
      int nt = tid >> 3, lanebase = (tid & 7) << 2;
      #pragma unroll 8
      for (int s = 0; s < H; s++){
        int ks = s >> 4, kl = s & 15, r = kl >> 3, cq = (kl & 7) >> 1, hf = kl & 1;
        int ui = ((ks*9 + nt)*32 + lanebase + cq)*2 + r;
        sum += hf2f(((unsigned short*)&XH[ui])[hf]) * __ldg(&fcw[s]);
      }
      out[a] = sum;
    }
  }
}

// ---------------- launch ----------------
extern "C" void kernel_launch(void* const* d_in, const int* in_sizes, int n_in,
                              void* d_out, int out_size){
  const float* seq  = (const float*)d_in[0];
  const void*  ei   = d_in[1];
  const float* nf   = (const float*)d_in[3];
  const float* gw   = (const float*)d_in[5];
  const float* gb   = (const float*)d_in[6];
  const float* wih0 = (const float*)d_in[7];
  const float* whh0 = (const float*)d_in[8];
  const float* bih0 = (const float*)d_in[9];
  const float* bhh0 = (const float*)d_in[10];
  const float* wih1 = (const float*)d_in[11];
  const float* whh1 = (const float*)d_in[12];
  const float* bih1 = (const float*)d_in[13];
  const float* bhh1 = (const float*)d_in[14];
  const float* fcw  = (const float*)d_in[15];
  const float* fcb  = (const float*)d_in[16];
  float* out = (float*)d_out;

  k_reset<<<1,1>>>();
  k_init<<<(N_NODES + 255)/256, 256>>>((const int*)ei);
  k_degedge<<<(N_EDGES + 255)/256, 256>>>(ei);
  k_scan<<<1, 1024>>>();
  k_place<<<(N_EDGES + 255)/256, 256>>>(ei);
  k_xw<<<(N_NODES + 15)/16, 256>>>(nf, gw);
  k_gather<<<(N_NODES + 3)/4, 256>>>(gb);
  k_gpf<<<666, 256>>>(wih0, bih0, bhh0);
  k_wf<<<(106496 + 255)/256, 256>>>(wih0, whh0, wih1, whh1);

  cudaFuncSetAttribute(k_mega, cudaFuncAttributeMaxDynamicSharedMemorySize, SMEM_B);
  k_mega<<<NBLK, THREADS, SMEM_B>>>(seq, bih1, bhh1, fcw, fcb, out);
}

// round 14
// speedup vs baseline: 1.3382x; 1.0026x over previous
#include <cuda_runtime.h>
#include <cuda_fp16.h>
#include <cstdint>

#define N_NODES 10000
#define N_EDGES 160000
#define F_NODE  128
#define C_GCN   64
#define S_SEQ   32
#define T_SEQ   96
#define H       128
#define NP      72
#define NBLK    148
#define NPAD    (NBLK*NP)      /* 10656 */
#define THREADS 256

#define XF_U    10368          /* 18 kslots x 9 ntiles x 32 lanes x 2 u32 */
#define ZERO_U  (XF_U + 2*9216)            /* XH + c0 + c1 = 28800 u32 */
#define W0S_U4  3072                       /* 3 static k16 chunks */
#define RING_U4 3072                       /* 3-slot cp.async ring */
#define SMEM_B  ((ZERO_U + (W0S_U4 + RING_U4)*4)*4)   /* 213504 B */

// ---------------- device globals ----------------
__device__ int    g_i32;                   // sticky, idempotent across replays
__device__ float  g_deg [N_NODES];
__device__ float  g_dinv[N_NODES];
__device__ float  g_xwS [N_NODES*C_GCN];   // raw nf@gw (unnormalized)
__device__ int    g_off [N_NODES];
__device__ int    g_fill[N_NODES];
__device__ int    g_src [N_EDGES];
__device__ float  g_gcnT[C_GCN*N_NODES];
__device__ float4 g_gpF [NBLK*8*4*9*32];   // [blk][w][g][nt][lane] d-frag f32x4
__device__ uint4  g_WF  [26624];           // fp16 A-frags: layer0 10240, layer1 16384

__device__ __forceinline__ int eidx(const void* ei, int idx){
  if (g_i32) return ((const int*)ei)[idx];
  return (int)((const long long*)ei)[idx];
}

__device__ __forceinline__ unsigned short hfbits(float v){
  __half h = __float2half_rn(v);
  return *(unsigned short*)&h;
}
__device__ __forceinline__ float hf2f(unsigned short u){
  return __half2float(*(__half*)&u);
}

// ---------------- GCN prep ----------------
// init deg/fill + detect int32-vs-int64 (g_i32 zero-init'd; atomicOr idempotent)
__global__ void k_init(const int* ei){
  int i = blockIdx.x*blockDim.x + threadIdx.x;
  if (i < N_NODES){ g_deg[i] = 1.f; g_fill[i] = 0; }
  int any = 0;
  for (int e = i; e < N_EDGES; e += gridDim.x*blockDim.x) any |= ei[2*e+1];
  if (__syncthreads_or(any)) { if (threadIdx.x == 0) atomicOr(&g_i32, 1); }
}

// fused independent work: degedge atomics | raw xw GEMM | weight A-frag build
__global__ void k_work1(const void* ei, const float* __restrict__ nf,
                        const float* __restrict__ gw,
                        const float* __restrict__ wih0, const float* __restrict__ whh0,
                        const float* __restrict__ wih1, const float* __restrict__ whh1){
  int b = blockIdx.x, tid = threadIdx.x;
  if (b < 625){
    int e = b*256 + tid;
    if (e < N_EDGES) atomicAdd(&g_deg[eidx(ei, N_EDGES + e)], 1.f);
  } else if (b < 1250){
    __shared__ float gws[F_NODE*C_GCN];
    for (int i = tid; i < F_NODE*C_GCN/4; i += 256)
      ((float4*)gws)[i] = ((const float4*)gw)[i];
    __syncthreads();
    int q = tid & 15, nl = tid >> 4;
    int n = (b - 625)*16 + nl;
    if (n >= N_NODES) return;
    float4 acc = {0.f, 0.f, 0.f, 0.f};
    const float4* nfr = (const float4*)(nf + (size_t)n*F_NODE);
    #pragma unroll 4
    for (int k4 = 0; k4 < 32; k4++){
      float4 a = nfr[k4];
      #pragma unroll
      for (int kk = 0; kk < 4; kk++){
        float av = (kk==0)?a.x:(kk==1)?a.y:(kk==2)?a.z:a.w;
        const float* gr = &gws[(k4*4 + kk)*C_GCN + q*4];
        acc.x += av*gr[0]; acc.y += av*gr[1]; acc.z += av*gr[2]; acc.w += av*gr[3];
      }
    }
    *(float4*)&g_xwS[n*C_GCN + q*4] = acc;
  } else {
    int idx = (b - 1250)*256 + tid;
    if (idx >= 106496) return;
    int reg = idx & 3, l = (idx >> 2) & 31;
    int w = (idx >> 7) & 7, g = (idx >> 10) & 3, k16 = idx >> 12;
    int layer = (k16 >= 10);
    int k16l = layer ? k16 - 10 : k16;
    int T = l >> 2, cq = l & 3;
    int row  = T + 8*(reg & 1);
    int colb = 2*cq + 8*(reg >> 1);
    int m = g*128 + w*16 + row;
    int k = k16l*16 + colb;
    float v0, v1;
    if (layer){
      if (k < 128){ v0 = whh1[m*128 + k];       v1 = whh1[m*128 + k + 1]; }
      else        { v0 = wih1[m*128 + k - 128]; v1 = wih1[m*128 + k - 127]; }
    } else {
      if (k < 128){ v0 = whh0[m*128 + k];       v1 = whh0[m*128 + k + 1]; }
      else        { v0 = wih0[m*96 + k - 128];  v1 = wih0[m*96 + k - 127]; }
    }
    ((uint32_t*)g_WF)[idx] = ((uint32_t)hfbits(v1) << 16) | (uint32_t)hfbits(v0);
  }
}

// exclusive prefix sum of (deg-1) via shfl warp-scan; also emits dinv
__global__ void k_scan(){
  __shared__ int wsum[32];
  int tid = threadIdx.x, lane = tid & 31, wid = tid >> 5;
  int base = tid*10;
  int v[10], s = 0;
  #pragma unroll
  for (int i = 0; i < 10; i++){
    int n = base + i;
    int c = (n < N_NODES) ? ((int)g_deg[n] - 1) : 0;
    v[i] = s; s += c;
    if (n < N_NODES) g_dinv[n] = rsqrtf(g_deg[n]);
  }
  int pre = s;
  #pragma unroll
  for (int d = 1; d < 32; d <<= 1){
    int x = __shfl_up_sync(0xffffffff, pre, d);
    if (lane >= d) pre += x;
  }
  if (lane == 31) wsum[wid] = pre;
  __syncthreads();
  if (wid == 0){
    int x = wsum[lane];
    #pragma unroll
    for (int d = 1; d < 32; d <<= 1){
      int y = __shfl_up_sync(0xffffffff, x, d);
      if (lane >= d) x += y;
    }
    wsum[lane] = x;
  }
  __syncthreads();
  int add = ((wid > 0) ? wsum[wid-1] : 0) + (pre - s);
  #pragma unroll
  for (int i = 0; i < 10; i++){
    int n = base + i;
    if (n < N_NODES) g_off[n] = add + v[i];
  }
}

// counting-sort edge sources by destination node
__global__ void k_place(const void* ei){
  int e = blockIdx.x*blockDim.x + threadIdx.x;
  if (e >= N_EDGES) return;
  int col = eidx(ei, N_EDGES + e);
  int pos = atomicAdd(&g_fill[col], 1);
  g_src[g_off[col] + pos] = eidx(ei, e);
}

// gather-sum incoming messages (src-normalized) + self loop, normalize, +bias
__global__ void k_gather(const float* __restrict__ gb){
  int tid = threadIdx.x;
  int c = tid & 63, nl = tid >> 6;
  int n = blockIdx.x*4 + nl;
  if (n >= N_NODES) return;
  int off = g_off[n];
  int cnt = (int)g_deg[n] - 1;
  float dn = g_dinv[n];
  float s = g_xwS[n*C_GCN + c] * dn;
  for (int j = 0; j < cnt; j++){
    int src = g_src[off + j];
    s += g_xwS[src*C_GCN + c] * g_dinv[src];
  }
  g_gcnT[c*N_NODES + n] = dn*s + __ldg(&gb[c]);
}

// gpart (gcn + both layer-0 biases) baked into D-fragment layout.
__global__ void k_gpf(const float* __restrict__ wih0, const float* __restrict__ bih0,
                      const float* __restrict__ bhh0){
  int gt = blockIdx.x*blockDim.x + threadIdx.x;
  int warp = gt >> 5, lane = gt & 31;
  int mg = warp & 15;
  int pw = warp >> 4;
  int p = pw*32 + lane;
  if (p >= NPAD) return;
  int a = p < N_NODES ? p : N_NODES - 1;
  float gc[64];
  #pragma unroll
  for (int j = 0; j < 64; j++) gc[j] = g_gcnT[j*N_NODES + a];
  int blk = p / NP, pl = p - blk*NP;
  int nt = pl >> 3, n8 = pl & 7, cq = n8 >> 1, dn = n8 & 1;
  #pragma unroll 1
  for (int mi = 0; mi < 32; mi++){
    int m = mg*32 + mi;
    float s = __ldg(&bih0[m]) + __ldg(&bhh0[m]);
    #pragma unroll
    for (int j = 0; j < 64; j++) s += gc[j] * __ldg(&wih0[m*96 + 32 + j]);
    int g = m >> 7, ml = m & 127, w = ml >> 4, t8 = ml & 15, T = t8 & 7, hf = t8 >> 3;
    int lane2 = T*4 + cq, r = hf*2 + dn;
    ((float*)g_gpF)[((((blk*8 + w)*4 + g)*9 + nt)*32 + lane2)*4 + r] = s;
  }
}

// ---------------- mega kernel ----------------
__device__ __forceinline__ float tanh_a(float x){
  float r; asm("tanh.approx.f32 %0, %1;" : "=f"(r) : "f"(x)); return r;
}
__device__ __forceinline__ float sig_a(float x){
  return fmaf(0.5f, tanh_a(0.5f*x), 0.5f);
}

__device__ __forceinline__ void mma_f16(float* d, const uint32_t* a, uint2 b){
  asm volatile("mma.sync.aligned.m16n8k16.row.col.f32.f16.f16.f32 "
               "{%0,%1,%2,%3}, {%4,%5,%6,%7}, {%8,%9}, {%0,%1,%2,%3};"
               : "+f"(d[0]), "+f"(d[1]), "+f"(d[2]), "+f"(d[3])
               : "r"(a[0]), "r"(a[1]), "r"(a[2]), "r"(a[3]), "r"(b.x), "r"(b.y));
}

__device__ __forceinline__ void mma_block(const uint32_t* __restrict__ XH,
                                          const uint4 a[4], float acc[36][4],
                                          int ks, int l){
  #pragma unroll
  for (int nt = 0; nt < 9; nt++){
    uint2 bh = *(const uint2*)&XH[((ks*9 + nt)*32 + l)*2];
    #pragma unroll
    for (int g = 0; g < 4; g++)
      mma_f16(acc[g*9+nt], (const uint32_t*)&a[g], bh);
  }
}

__device__ __forceinline__ void ld_frags(uint4 a[4], const uint4* __restrict__ base, int o){
  #pragma unroll
  for (int g = 0; g < 4; g++) a[g] = base[g*256 + o];
}

__device__ __forceinline__ void cp_issue(uint32_t ring_addr, int slot, int p, int o){
  const char* src = (const char*)(g_WF + (p + 3)*1024 + o);
  uint32_t dst = ring_addr + (uint32_t)(slot*16384 + o*16);
  #pragma unroll
  for (int g = 0; g < 4; g++){
    asm volatile("{ .reg .u64 gp; cvta.to.global.u64 gp, %1;"
                 " cp.async.cg.shared.global [%0], [gp], 16; }"
                 :: "r"(dst + g*4096), "l"(src + (size_t)g*4096) : "memory");
  }
  asm volatile("cp.async.commit_group;" ::: "memory");
}

#define PIPE_STEP(ACC, KS) do { \
  int sI = sA + 2; if (sI >= 3) sI -= 3; \
  int pI = pA + 2; if (pI >= 23) pI -= 23; \
  cp_issue(ring_addr, sI, pI, o); \
  mma_block(XH, a_cur, (ACC), (KS), l); \
  asm volatile("cp.async.wait_group 1;" ::: "memory"); \
  sA = (sA + 1 == 3) ? 0 : sA + 1; \
  pA = (pA + 1 == 23) ? 0 : pA + 1; \
  ld_frags(a_cur, Wring + sA*1024, o); \
} while(0)

__device__ __forceinline__ void epilogue(float acc[36][4], float* csm,
                                         uint32_t* XH, int w, int l, int ksbase){
  int T = l >> 2, cq = l & 3;
  int ks = ksbase + w;
  int s_lo = w*16 + T, s_hi = s_lo + 8;
  #pragma unroll
  for (int nt = 0; nt < 9; nt++){
    int n0 = nt*8 + 2*cq;
    float2 cl = *(float2*)&csm[s_lo*NP + n0];
    float2 ch = *(float2*)&csm[s_hi*NP + n0];
    float cold[4] = {cl.x, cl.y, ch.x, ch.y};
    float2 nl, nh;
    #pragma unroll
    for (int r = 0; r < 4; r++){
      int half = r >> 1;
      float gi = acc[nt][r], gf = acc[9+nt][r], gz = acc[18+nt][r], go = acc[27+nt][r];
      float cn = sig_a(gf)*cold[r] + sig_a(gi)*tanh_a(gz);
      if (r == 0) nl.x = cn; else if (r == 1) nl.y = cn;
      else if (r == 2) nh.x = cn; else nh.y = cn;
      float h = sig_a(go)*tanh_a(cn);
      int n = n0 + (r & 1);
      int lane = ((n & 7) << 2) + (T >> 1);
      int ui = ((ks*9 + nt)*32 + lane)*2 + half;
      ((unsigned short*)&XH[ui])[T & 1] = hfbits(h);
    }
    *(float2*)&csm[s_lo*NP + n0] = nl;
    *(float2*)&csm[s_hi*NP + n0] = nh;
  }
}

__device__ __forceinline__ void stage_seq(const float* __restrict__ seq, int base, int t,
                                          uint32_t* XH, int tid){
  for (int idx = tid; idx < NP*S_SEQ; idx += THREADS){
    int nl = idx >> 5, i = idx & 31;
    int a = base + nl; if (a >= N_NODES) a = N_NODES - 1;
    float v = seq[(size_t)a*(T_SEQ*S_SEQ) + t*S_SEQ + i];
    int ks = 16 + (i >> 4), kl = i & 15;
    int r = kl >> 3, cq = (kl & 7) >> 1, hf = kl & 1;
    int lane = ((nl & 7) << 2) + cq;
    int nt = nl >> 3;
    int ui = ((ks*9 + nt)*32 + lane)*2 + r;
    ((unsigned short*)&XH[ui])[hf] = hfbits(v);
  }
}

__global__ void __launch_bounds__(THREADS)
k_mega(const float* __restrict__ seq, const float* __restrict__ bih1,
       const float* __restrict__ bhh1, const float* __restrict__ fcw,
       const float* __restrict__ fcb, float* __restrict__ out){
  extern __shared__ uint32_t smu[];
  uint32_t* XH = smu;
  float* c0 = (float*)(smu + XF_U);
  float* c1 = c0 + 9216;
  uint4* W0S   = (uint4*)(smu + ZERO_U);
  uint4* Wring = W0S + W0S_U4;
  int tid = threadIdx.x, w = tid >> 5, l = tid & 31;
  int blk = blockIdx.x, base = blk*NP;
  int T = l >> 2, o = w*32 + l;
  uint32_t ring_addr;
  asm("{ .reg .u64 t; cvta.to.shared.u64 t, %1; cvt.u32.u64 %0, t; }"
      : "=r"(ring_addr) : "l"((const void*)Wring));

  for (int i = tid; i < ZERO_U; i += THREADS) smu[i] = 0;
  for (int i = tid; i < W0S_U4; i += THREADS) W0S[i] = g_WF[i];  // static chunks 0..2
  __syncthreads();
  stage_seq(seq, base, 0, XH, tid);

  float b1v[4][2];
  #pragma unroll
  for (int g = 0; g < 4; g++)
    #pragma unroll
    for (int hf = 0; hf < 2; hf++){
      int m = g*128 + w*16 + T + 8*hf;
      b1v[g][hf] = __ldg(&bih1[m]) + __ldg(&bhh1[m]);
    }
  __syncthreads();

  // ---- cp.async pipeline prologue ----
  uint4 a_cur[4];
  int sA = 0, pA = 0;
  cp_issue(ring_addr, 0, 0, o);
  cp_issue(ring_addr, 1, 1, o);
  asm volatile("cp.async.wait_group 1;" ::: "memory");
  ld_frags(a_cur, Wring, o);

  const float4* gp = g_gpF + (blk*8 + w)*1152;

  for (int t = 0; t < T_SEQ; t++){
    // ================= phase A: gemm0 (ks 8..17) =================
    float acc0[36][4];
    #pragma unroll
    for (int g = 0; g < 4; g++)
      #pragma unroll
      for (int nt = 0; nt < 9; nt++){
        float4 v = __ldg(&gp[g*288 + nt*32 + l]);
        acc0[g*9+nt][0] = v.x; acc0[g*9+nt][1] = v.y;
        acc0[g*9+nt][2] = v.z; acc0[g*9+nt][3] = v.w;
      }
    {
      uint4 s_cur[4], s_nxt[4];
      ld_frags(s_cur, W0S, o);
      #pragma unroll
      for (int k = 0; k < 3; k++){
        if (k < 2) ld_frags(s_nxt, W0S + (k+1)*1024, o);
        mma_block(XH, s_cur, acc0, 8 + k, l);
        #pragma unroll
        for (int g = 0; g < 4; g++) s_cur[g] = s_nxt[g];
      }
    }
    #pragma unroll 1
    for (int j = 0; j < 7; j++) PIPE_STEP(acc0, 11 + j);
    __syncthreads();

    // ===== phase B: epi0 + stage_seq + gemm1 ks 0..7 =====
    epilogue(acc0, c0, XH, w, l, 8);
    if (t + 1 < T_SEQ) stage_seq(seq, base, t + 1, XH, tid);
    float acc1[36][4];
    #pragma unroll
    for (int g = 0; g < 4; g++)
      #pragma unroll
      for (int nt = 0; nt < 9; nt++){
        acc1[g*9+nt][0] = b1v[g][0]; acc1[g*9+nt][1] = b1v[g][0];
        acc1[g*9+nt][2] = b1v[g][1]; acc1[g*9+nt][3] = b1v[g][1];
      }
    #pragma unroll 1
    for (int j = 0; j < 8; j++) PIPE_STEP(acc1, j);
    __syncthreads();

    // ===== phase C: gemm1 ks 8..15 + epi1 (no trailing barrier) =====
    #pragma unroll 1
    for (int j = 8; j < 16; j++) PIPE_STEP(acc1, j);
    epilogue(acc1, c1, XH, w, l, 0);
  }
  asm volatile("cp.async.wait_group 0;" ::: "memory");
  __syncthreads();   // make final epi1 h1 writes visible to the FC below

  if (tid < NP){
    int a = base + tid;
    if (a < N_NODES){
      float sum = __ldg(fcb);
      int nt = tid >> 3, lanebase = (tid & 7) << 2;
      #pragma unroll 8
      for (int s = 0; s < H; s++){
        int ks = s >> 4, kl = s & 15, r = kl >> 3, cq = (kl & 7) >> 1, hf = kl & 1;
        int ui = ((ks*9 + nt)*32 + lanebase + cq)*2 + r;
        sum += hf2f(((unsigned short*)&XH[ui])[hf]) * __ldg(&fcw[s]);
      }
      out[a] = sum;
    }
  }
}

// ---------------- launch ----------------
extern "C" void kernel_launch(void* const* d_in, const int* in_sizes, int n_in,
                              void* d_out, int out_size){
  const float* seq  = (const float*)d_in[0];
  const void*  ei   = d_in[1];
  const float* nf   = (const float*)d_in[3];
  const float* gw   = (const float*)d_in[5];
  const float* gb   = (const float*)d_in[6];
  const float* wih0 = (const float*)d_in[7];
  const float* whh0 = (const float*)d_in[8];
  const float* bih0 = (const float*)d_in[9];
  const float* bhh0 = (const float*)d_in[10];
  const float* wih1 = (const float*)d_in[11];
  const float* whh1 = (const float*)d_in[12];
  const float* bih1 = (const float*)d_in[13];
  const float* bhh1 = (const float*)d_in[14];
  const float* fcw  = (const float*)d_in[15];
  const float* fcb  = (const float*)d_in[16];
  float* out = (float*)d_out;

  k_init<<<(N_NODES + 255)/256, 256>>>((const int*)ei);
  k_work1<<<1666, 256>>>(ei, nf, gw, wih0, whh0, wih1, whh1);
  k_scan<<<1, 1024>>>();
  k_place<<<(N_EDGES + 255)/256, 256>>>(ei);
  k_gather<<<(N_NODES + 3)/4, 256>>>(gb);
  k_gpf<<<666, 256>>>(wih0, bih0, bhh0);

  cudaFuncSetAttribute(k_mega, cudaFuncAttributeMaxDynamicSharedMemorySize, SMEM_B);
  k_mega<<<NBLK, THREADS, SMEM_B>>>(seq, bih1, bhh1, fcw, fcb, out);
}